// round 9
// baseline (speedup 1.0000x reference)
#include <cuda_runtime.h>
#include <math.h>

// ---------------- problem constants ----------------
constexpr int kB   = 8;
constexpr int kN   = 2048;
constexpr int kM   = 512;
constexpr int kCIN = 256;
constexpr int kCFP = 128;
constexpr int kC   = 128;   // C_OUT
constexpr int kCG  = 512;
constexpr int kH   = 8;
constexpr int kD   = 16;    // head dim

// ---------------- scratch (no allocation allowed) ----------------
__device__ float g_interp[kB * kCIN * kN];
__device__ float g_h1    [kB * kCIN * kN];
__device__ float g_nf    [kB * kCFP * kN];
__device__ float g_qf    [kB * kC   * kN];
__device__ float g_vf    [kB * kC   * kN];
__device__ float g_Q     [kB * kC   * kN];
__device__ float g_K     [kB * kC   * kN];
__device__ float g_V     [kB * kC   * kN];
__device__ float g_O     [kB * kC   * kN];
__device__ float g_y     [kB * kC   * kN];
__device__ float g_gb    [kB * kC];
__device__ int   g_idx   [kB * kN * 3];
__device__ float g_w     [kB * kN * 3];

// pre-split transposed weights: hi/lo, layout [ic][oc]
constexpr int OFF_FP1 = 0;                 // 256x256
constexpr int OFF_FP2 = OFF_FP1 + 65536;   // 128x256
constexpr int OFF_QM  = OFF_FP2 + 32768;   // 128x128
constexpr int OFF_WQ  = OFF_QM  + 16384;
constexpr int OFF_WK  = OFF_WQ  + 16384;
constexpr int OFF_WV  = OFF_WK  + 16384;
constexpr int OFF_WP  = OFF_WV  + 16384;
constexpr int OFF_OM  = OFF_WP  + 16384;
constexpr int W_TOTAL = OFF_OM  + 16384;   // 196608
__device__ float g_whi[W_TOTAL];
__device__ float g_wlo[W_TOTAL];

// ---------------- helpers ----------------
__device__ __forceinline__ float ex2(float x) {
    float y;
    asm("ex2.approx.f32 %0, %1;" : "=f"(y) : "f"(x));
    return y;
}
__device__ __forceinline__ unsigned cvt_tf32(float f) {
    unsigned u;
    asm("cvt.rna.tf32.f32 %0, %1;" : "=r"(u) : "f"(f));
    return u;
}
__device__ __forceinline__ void mma_tf32(float c[4], const unsigned a[4],
                                         unsigned b0, unsigned b1) {
    asm volatile(
        "mma.sync.aligned.m16n8k8.row.col.f32.tf32.tf32.f32 "
        "{%0,%1,%2,%3}, {%4,%5,%6,%7}, {%8,%9}, {%0,%1,%2,%3};"
        : "+f"(c[0]), "+f"(c[1]), "+f"(c[2]), "+f"(c[3])
        : "r"(a[0]), "r"(a[1]), "r"(a[2]), "r"(a[3]), "r"(b0), "r"(b1));
}
__device__ __forceinline__ float2 split2(float x) {
    const float hf = __uint_as_float(cvt_tf32(x));
    return make_float2(hf, x - hf);
}
__device__ __forceinline__ void cp16(void* dst, const void* src) {
    unsigned d = (unsigned)__cvta_generic_to_shared(dst);
    asm volatile("cp.async.ca.shared.global [%0], [%1], 16;" :: "r"(d), "l"(src));
}

// ---------------- weight pre-split (hi/lo, transposed) ----------------
struct PSArgs {
    const float* src[8];
    float* hi[8];
    float* lo[8];
    int OC[8];
    int IC[8];
};
__global__ __launch_bounds__(256) void presplit_kernel(PSArgs a) {
    const int s  = blockIdx.y;
    const int OC = a.OC[s], IC = a.IC[s];
    const int n  = OC * IC;
    for (int i = blockIdx.x * 256 + threadIdx.x; i < n; i += gridDim.x * 256) {
        const int oc = i / IC, ic = i - oc * IC;
        const float x = a.src[s][i];
        const float h = __uint_as_float(cvt_tf32(x));
        a.hi[s][(size_t)ic * OC + oc] = h;
        a.lo[s][(size_t)ic * OC + oc] = x - h;
    }
}

// ---------------- three_nn ----------------
__global__ __launch_bounds__(128) void knn_kernel(
    const float* __restrict__ up_xyz, const float* __restrict__ xyz,
    int* __restrict__ idxo, float* __restrict__ wo)
{
    __shared__ float sx[kM * 3];
    const int b = blockIdx.y;
    for (int i = threadIdx.x; i < kM * 3; i += 128) sx[i] = xyz[b * kM * 3 + i];
    __syncthreads();

    const int n = blockIdx.x * 128 + threadIdx.x;
    const float px = up_xyz[(b * kN + n) * 3 + 0];
    const float py = up_xyz[(b * kN + n) * 3 + 1];
    const float pz = up_xyz[(b * kN + n) * 3 + 2];

    float d0 = 1e30f, d1 = 1e30f, d2 = 1e30f;
    int   i0 = 0,     i1 = 0,     i2 = 0;
    for (int m = 0; m < kM; m++) {
        float dx = sx[m * 3 + 0] - px;
        float dy = sx[m * 3 + 1] - py;
        float dz = sx[m * 3 + 2] - pz;
        float d  = dx * dx + dy * dy + dz * dz;
        if (d < d2) {
            if (d < d1) {
                if (d < d0) { d2 = d1; i2 = i1; d1 = d0; i1 = i0; d0 = d; i0 = m; }
                else        { d2 = d1; i2 = i1; d1 = d;  i1 = m; }
            } else          { d2 = d;  i2 = m; }
        }
    }
    d0 = fmaxf(d0, 1e-10f); d1 = fmaxf(d1, 1e-10f); d2 = fmaxf(d2, 1e-10f);
    float r0 = 1.0f / d0, r1 = 1.0f / d1, r2 = 1.0f / d2;
    float s  = r0 + r1 + r2;
    const int base = (b * kN + n) * 3;
    idxo[base] = i0; idxo[base + 1] = i1; idxo[base + 2] = i2;
    wo[base] = r0 / s; wo[base + 1] = r1 / s; wo[base + 2] = r2 / s;
}

// ---------------- inverse-distance interpolation ----------------
__global__ void interp_kernel(
    const float* __restrict__ feat, const int* __restrict__ idx3,
    const float* __restrict__ w3, float* __restrict__ out)
{
    const int b = blockIdx.z, c = blockIdx.y;
    const int n = blockIdx.x * 256 + threadIdx.x;
    const float* f = feat + ((size_t)b * kCIN + c) * kM;
    const int base = (b * kN + n) * 3;
    const int j0 = idx3[base], j1 = idx3[base + 1], j2 = idx3[base + 2];
    const float w0 = w3[base], w1 = w3[base + 1], w2 = w3[base + 2];
    out[((size_t)b * kCIN + c) * kN + n] = w0 * f[j0] + w1 * f[j1] + w2 * f[j2];
}

// ---------------- 3xTF32 GEMM: pre-split W, 128oc x 64n tile, 128 thr ----------------
// WhiT/WloT layout [ic][OC], pre-offset by oc0 (row stride ldw = OC).
__device__ __forceinline__ void gemm3_tile(
    const float* __restrict__ WhiT, const float* __restrict__ WloT,
    const float* __restrict__ Xb, float* __restrict__ Yb,
    int ldw, int IC, int n0,
    const float* bias, const float* gamma, const float* beta,
    const float* addB, int relu,
    float (*WsH)[132], float (*WsL)[132], float2 (*Xs)[68])
{
    const int tid  = threadIdx.x;       // 0..127
    const int w    = tid >> 5;
    const int lane = tid & 31;
    const int g    = lane >> 2;
    const int t    = lane & 3;
    const int ocw  = w * 32;

    const int kw = tid >> 3, cw = (tid & 7) * 16;   // W loader
    const int kx = tid >> 3, nx = (tid & 7) * 8;    // X loader

    float c[2][8][4];
#pragma unroll
    for (int i = 0; i < 2; i++)
#pragma unroll
        for (int j = 0; j < 8; j++)
#pragma unroll
            for (int r = 0; r < 4; r++) c[i][j][r] = 0.0f;

    for (int k0 = 0; k0 < IC; k0 += 16) {
        const float4 xa = *(const float4*)&Xb[(size_t)(k0 + kx) * kN + n0 + nx];
        const float4 xb = *(const float4*)&Xb[(size_t)(k0 + kx) * kN + n0 + nx + 4];
        __syncthreads();    // WAR: previous consume done
        const float* wh = WhiT + (size_t)(k0 + kw) * ldw + cw;
        const float* wl = WloT + (size_t)(k0 + kw) * ldw + cw;
#pragma unroll
        for (int q = 0; q < 4; q++) {
            cp16(&WsH[kw][cw + q * 4], wh + q * 4);
            cp16(&WsL[kw][cw + q * 4], wl + q * 4);
        }
        asm volatile("cp.async.commit_group;");
        Xs[kx][nx + 0] = split2(xa.x); Xs[kx][nx + 1] = split2(xa.y);
        Xs[kx][nx + 2] = split2(xa.z); Xs[kx][nx + 3] = split2(xa.w);
        Xs[kx][nx + 4] = split2(xb.x); Xs[kx][nx + 5] = split2(xb.y);
        Xs[kx][nx + 6] = split2(xb.z); Xs[kx][nx + 7] = split2(xb.w);
        asm volatile("cp.async.wait_group 0;" ::: "memory");
        __syncthreads();

#pragma unroll
        for (int ks = 0; ks < 2; ks++) {
            const int r0 = ks * 8 + t, r1 = ks * 8 + t + 4;
            unsigned ahi[2][4], alo[2][4];
#pragma unroll
            for (int i = 0; i < 2; i++) {
                const int oc = ocw + i * 16 + g;
                ahi[i][0] = __float_as_uint(WsH[r0][oc]);
                ahi[i][1] = __float_as_uint(WsH[r0][oc + 8]);
                ahi[i][2] = __float_as_uint(WsH[r1][oc]);
                ahi[i][3] = __float_as_uint(WsH[r1][oc + 8]);
                alo[i][0] = __float_as_uint(WsL[r0][oc]);
                alo[i][1] = __float_as_uint(WsL[r0][oc + 8]);
                alo[i][2] = __float_as_uint(WsL[r1][oc]);
                alo[i][3] = __float_as_uint(WsL[r1][oc + 8]);
            }
#pragma unroll
            for (int j = 0; j < 8; j++) {
                const int nc = j * 8 + g;
                const float2 b0 = Xs[r0][nc];
                const float2 b1 = Xs[r1][nc];
                const unsigned bh0 = __float_as_uint(b0.x), bl0 = __float_as_uint(b0.y);
                const unsigned bh1 = __float_as_uint(b1.x), bl1 = __float_as_uint(b1.y);
#pragma unroll
                for (int i = 0; i < 2; i++) {
                    mma_tf32(c[i][j], ahi[i], bh0, bh1);
                    mma_tf32(c[i][j], alo[i], bh0, bh1);
                    mma_tf32(c[i][j], ahi[i], bl0, bl1);
                }
            }
        }
    }

    const float rs = rsqrtf(1.0f + 1e-5f);
#pragma unroll
    for (int i = 0; i < 2; i++) {
#pragma unroll
        for (int half = 0; half < 2; half++) {
            const int oc = ocw + i * 16 + g + half * 8;
            const float bi = bias  ? bias[oc]       : 0.0f;
            const float sc = gamma ? gamma[oc] * rs : 1.0f;
            const float bb = gamma ? beta[oc]       : 0.0f;
#pragma unroll
            for (int j = 0; j < 8; j++) {
                const int nc = n0 + j * 8 + 2 * t;
                float v0 = fmaf(c[i][j][half * 2]     + bi, sc, bb);
                float v1 = fmaf(c[i][j][half * 2 + 1] + bi, sc, bb);
                if (addB) {
                    const float2 ad = *(const float2*)&addB[(size_t)oc * kN + nc];
                    v0 += ad.x; v1 += ad.y;
                }
                if (relu) { v0 = fmaxf(v0, 0.0f); v1 = fmaxf(v1, 0.0f); }
                *(float2*)&Yb[(size_t)oc * kN + nc] = make_float2(v0, v1);
            }
        }
    }
}

__global__ __launch_bounds__(128, 4) void gemm3(
    const float* __restrict__ WhiT, const float* __restrict__ WloT,
    const float* __restrict__ X, float* __restrict__ Y,
    const float* __restrict__ bias, const float* __restrict__ gamma,
    const float* __restrict__ beta, const float* __restrict__ add,
    int OC, int IC, int relu)
{
    __shared__ float  WsH[16][132];
    __shared__ float  WsL[16][132];
    __shared__ float2 Xs[16][68];
    const int b   = blockIdx.z;
    const int n0  = blockIdx.x * 64;
    const int oc0 = blockIdx.y * 128;
    gemm3_tile(WhiT + oc0, WloT + oc0,
               X + (size_t)b * IC * kN,
               Y + ((size_t)b * OC + oc0) * kN,
               OC, IC, n0,
               bias  ? bias  + oc0 : nullptr,
               gamma ? gamma + oc0 : nullptr,
               beta  ? beta  + oc0 : nullptr,
               add   ? add + ((size_t)b * OC + oc0) * kN : nullptr,
               relu, WsH, WsL, Xs);
}

__global__ __launch_bounds__(128, 4) void qkv3(
    const float* __restrict__ whi, const float* __restrict__ wlo,
    const float* __restrict__ qf, const float* __restrict__ vf,
    float* __restrict__ Q, float* __restrict__ K, float* __restrict__ V)
{
    __shared__ float  WsH[16][132];
    __shared__ float  WsL[16][132];
    __shared__ float2 Xs[16][68];
    const int b = blockIdx.z;
    const int y = blockIdx.y;
    const int off = (y == 0) ? OFF_WQ : (y == 1) ? OFF_WK : OFF_WV;
    const float* X = ((y == 0) ? qf : vf) + (size_t)b * kC * kN;
    float*       Y = ((y == 0) ? Q : (y == 1) ? K : V) + (size_t)b * kC * kN;
    gemm3_tile(whi + off, wlo + off, X, Y, kC, kC, blockIdx.x * 64,
               nullptr, nullptr, nullptr, nullptr, 0, WsH, WsL, Xs);
}

// ---------------- v_feat helpers ----------------
__global__ void gbias_kernel(const float* __restrict__ fuW, const float* __restrict__ gf,
                             float* __restrict__ gb)
{
    const int b = blockIdx.x, c = threadIdx.x;
    const float* w = fuW + (size_t)c * (3 + kCG) + 3;
    const float* g = gf + b * kCG;
    float s = 0.0f;
    for (int j = 0; j < kCG; j++) s = fmaf(w[j], g[j], s);
    gb[b * kC + c] = s;
}

__global__ void vfeat_kernel(
    const float* __restrict__ fuW, const float* __restrict__ fub,
    const float* __restrict__ fug, const float* __restrict__ fube,
    const float* __restrict__ gb, const float* __restrict__ up_xyz,
    float* __restrict__ vf)
{
    const int b = blockIdx.z, c = blockIdx.y;
    const int n = blockIdx.x * 256 + threadIdx.x;
    const float w0 = fuW[c * (3 + kCG) + 0];
    const float w1 = fuW[c * (3 + kCG) + 1];
    const float w2 = fuW[c * (3 + kCG) + 2];
    const float x = up_xyz[(b * kN + n) * 3 + 0];
    const float y = up_xyz[(b * kN + n) * 3 + 1];
    const float z = up_xyz[(b * kN + n) * 3 + 2];
    float a = gb[b * kC + c] + fub[c] + w0 * x + w1 * y + w2 * z;
    const float rs = rsqrtf(1.0f + 1e-5f);
    a = fmaf(a, fug[c] * rs, fube[c]);
    vf[((size_t)b * kC + c) * kN + n] = fmaxf(a, 0.0f);
}

// ---------------- tf32 MMA flash attention (no max tracking) ----------------
__global__ __launch_bounds__(128) void attn_mma(
    const float* __restrict__ Q, const float* __restrict__ K,
    const float* __restrict__ V, float* __restrict__ O)
{
    __shared__ float Ks[kD][72];
    __shared__ float Vs[kD][72];
    const int bh   = blockIdx.y;
    const int tid  = threadIdx.x;
    const int warp = tid >> 5;
    const int lane = tid & 31;
    const int g    = lane >> 2;
    const int t    = lane & 3;

    const float* Qb = Q + (size_t)bh * kD * kN;
    const float* Kb = K + (size_t)bh * kD * kN;
    const float* Vb = V + (size_t)bh * kD * kN;
    float*       Ob = O + (size_t)bh * kD * kN;

    const float ALPHA = 0.25f * 1.44269504088896340736f;
    const int q0 = blockIdx.x * 64 + warp * 16 + g;

    unsigned aq[2][4];
#pragma unroll
    for (int ks = 0; ks < 2; ks++) {
        aq[ks][0] = cvt_tf32(Qb[(size_t)(ks * 8 + t)     * kN + q0]     * ALPHA);
        aq[ks][1] = cvt_tf32(Qb[(size_t)(ks * 8 + t)     * kN + q0 + 8] * ALPHA);
        aq[ks][2] = cvt_tf32(Qb[(size_t)(ks * 8 + t + 4) * kN + q0]     * ALPHA);
        aq[ks][3] = cvt_tf32(Qb[(size_t)(ks * 8 + t + 4) * kN + q0 + 8] * ALPHA);
    }

    float o0[4] = {0.f, 0.f, 0.f, 0.f};
    float o1[4] = {0.f, 0.f, 0.f, 0.f};
    float l0 = 0.f, l1 = 0.f;

    const int ld_d = tid >> 3;
    const int ld_k = (tid & 7) * 8;

    for (int kt = 0; kt < kN / 64; kt++) {
        const int k0 = kt * 64;
        __syncthreads();
        *(float4*)&Ks[ld_d][ld_k]     = *(const float4*)&Kb[(size_t)ld_d * kN + k0 + ld_k];
        *(float4*)&Ks[ld_d][ld_k + 4] = *(const float4*)&Kb[(size_t)ld_d * kN + k0 + ld_k + 4];
        *(float4*)&Vs[ld_d][ld_k]     = *(const float4*)&Vb[(size_t)ld_d * kN + k0 + ld_k];
        *(float4*)&Vs[ld_d][ld_k + 4] = *(const float4*)&Vb[(size_t)ld_d * kN + k0 + ld_k + 4];
        __syncthreads();

#pragma unroll
        for (int nt = 0; nt < 8; nt++) {
            float c[4] = {0.f, 0.f, 0.f, 0.f};
#pragma unroll
            for (int ks = 0; ks < 2; ks++) {
                const unsigned kb0 = __float_as_uint(Ks[ks * 8 + t][nt * 8 + g]);
                const unsigned kb1 = __float_as_uint(Ks[ks * 8 + t + 4][nt * 8 + g]);
                mma_tf32(c, aq[ks], kb0, kb1);
            }
            const float p0 = ex2(c[0]);
            const float p1 = ex2(c[1]);
            const float p2 = ex2(c[2]);
            const float p3 = ex2(c[3]);
            l0 += p0 + p1;
            l1 += p2 + p3;
            const unsigned pa[4] = {__float_as_uint(p0), __float_as_uint(p2),
                                    __float_as_uint(p1), __float_as_uint(p3)};
#pragma unroll
            for (int dt = 0; dt < 2; dt++) {
                const float2 bv = *(const float2*)&Vs[dt * 8 + g][nt * 8 + 2 * t];
                mma_tf32(dt ? o1 : o0, pa,
                         __float_as_uint(bv.x), __float_as_uint(bv.y));
            }
        }
    }

    l0 += __shfl_xor_sync(0xFFFFFFFFu, l0, 1);
    l0 += __shfl_xor_sync(0xFFFFFFFFu, l0, 2);
    l1 += __shfl_xor_sync(0xFFFFFFFFu, l1, 1);
    l1 += __shfl_xor_sync(0xFFFFFFFFu, l1, 2);
    const float inv0 = 1.0f / l0;
    const float inv1 = 1.0f / l1;

#pragma unroll
    for (int dt = 0; dt < 2; dt++) {
        const float* o = dt ? o1 : o0;
        const int d = dt * 8 + 2 * t;
        Ob[(size_t)d       * kN + q0]     = o[0] * inv0;
        Ob[(size_t)(d + 1) * kN + q0]     = o[1] * inv0;
        Ob[(size_t)d       * kN + q0 + 8] = o[2] * inv1;
        Ob[(size_t)(d + 1) * kN + q0 + 8] = o[3] * inv1;
    }
}

// ---------------- launch ----------------
extern "C" void kernel_launch(void* const* d_in, const int* in_sizes, int n_in,
                              void* d_out, int out_size)
{
    const float* up_xyz   = (const float*)d_in[0];
    const float* xyz      = (const float*)d_in[1];
    const float* features = (const float*)d_in[2];
    const float* gfeat    = (const float*)d_in[3];
    const float* fp1_W = (const float*)d_in[4];
    const float* fp1_b = (const float*)d_in[5];
    const float* fp1_g = (const float*)d_in[6];
    const float* fp1_be= (const float*)d_in[7];
    const float* fp2_W = (const float*)d_in[8];
    const float* fp2_b = (const float*)d_in[9];
    const float* fp2_g = (const float*)d_in[10];
    const float* fp2_be= (const float*)d_in[11];
    const float* qm_W  = (const float*)d_in[12];
    const float* qm_b  = (const float*)d_in[13];
    const float* qm_g  = (const float*)d_in[14];
    const float* qm_be = (const float*)d_in[15];
    const float* fu_W  = (const float*)d_in[16];
    const float* fu_b  = (const float*)d_in[17];
    const float* fu_g  = (const float*)d_in[18];
    const float* fu_be = (const float*)d_in[19];
    const float* Wq    = (const float*)d_in[20];
    const float* Wk    = (const float*)d_in[21];
    const float* Wv    = (const float*)d_in[22];
    const float* Wp    = (const float*)d_in[23];
    const float* bp    = (const float*)d_in[24];
    const float* om_W  = (const float*)d_in[25];
    const float* om_b  = (const float*)d_in[26];
    const float* om_g  = (const float*)d_in[27];
    const float* om_be = (const float*)d_in[28];

    float *interp, *h1, *nf, *qf, *vf, *Q, *K, *V, *O, *y, *gb, *w, *whi, *wlo;
    int* idx;
    cudaGetSymbolAddress((void**)&interp, g_interp);
    cudaGetSymbolAddress((void**)&h1,     g_h1);
    cudaGetSymbolAddress((void**)&nf,     g_nf);
    cudaGetSymbolAddress((void**)&qf,     g_qf);
    cudaGetSymbolAddress((void**)&vf,     g_vf);
    cudaGetSymbolAddress((void**)&Q,      g_Q);
    cudaGetSymbolAddress((void**)&K,      g_K);
    cudaGetSymbolAddress((void**)&V,      g_V);
    cudaGetSymbolAddress((void**)&O,      g_O);
    cudaGetSymbolAddress((void**)&y,      g_y);
    cudaGetSymbolAddress((void**)&gb,     g_gb);
    cudaGetSymbolAddress((void**)&idx,    g_idx);
    cudaGetSymbolAddress((void**)&w,      g_w);
    cudaGetSymbolAddress((void**)&whi,    g_whi);
    cudaGetSymbolAddress((void**)&wlo,    g_wlo);

    // 0) pre-split all weights into transposed hi/lo
    PSArgs ps;
    ps.src[0] = fp1_W; ps.hi[0] = whi + OFF_FP1; ps.lo[0] = wlo + OFF_FP1; ps.OC[0] = kCIN; ps.IC[0] = kCIN;
    ps.src[1] = fp2_W; ps.hi[1] = whi + OFF_FP2; ps.lo[1] = wlo + OFF_FP2; ps.OC[1] = kCFP; ps.IC[1] = kCIN;
    ps.src[2] = qm_W;  ps.hi[2] = whi + OFF_QM;  ps.lo[2] = wlo + OFF_QM;  ps.OC[2] = kC;   ps.IC[2] = kCFP;
    ps.src[3] = Wq;    ps.hi[3] = whi + OFF_WQ;  ps.lo[3] = wlo + OFF_WQ;  ps.OC[3] = kC;   ps.IC[3] = kC;
    ps.src[4] = Wk;    ps.hi[4] = whi + OFF_WK;  ps.lo[4] = wlo + OFF_WK;  ps.OC[4] = kC;   ps.IC[4] = kC;
    ps.src[5] = Wv;    ps.hi[5] = whi + OFF_WV;  ps.lo[5] = wlo + OFF_WV;  ps.OC[5] = kC;   ps.IC[5] = kC;
    ps.src[6] = Wp;    ps.hi[6] = whi + OFF_WP;  ps.lo[6] = wlo + OFF_WP;  ps.OC[6] = kC;   ps.IC[6] = kC;
    ps.src[7] = om_W;  ps.hi[7] = whi + OFF_OM;  ps.lo[7] = wlo + OFF_OM;  ps.OC[7] = kC;   ps.IC[7] = kC;
    presplit_kernel<<<dim3(32, 8), 256>>>(ps);

    // 1) three_nn + weights
    knn_kernel<<<dim3(kN / 128, kB), 128>>>(up_xyz, xyz, idx, w);
    // 2) inverse-distance interpolation -> (B,256,N)
    interp_kernel<<<dim3(kN / 256, kCIN, kB), 256>>>(features, idx, w, interp);
    // 3) fp mlp: CBL 256->256, CBL 256->128
    gemm3<<<dim3(kN / 64, kCIN / 128, kB), 128>>>(whi + OFF_FP1, wlo + OFF_FP1, interp, h1,
                                                  fp1_b, fp1_g, fp1_be, nullptr, kCIN, kCIN, 1);
    gemm3<<<dim3(kN / 64, 1, kB), 128>>>(whi + OFF_FP2, wlo + OFF_FP2, h1, nf,
                                         fp2_b, fp2_g, fp2_be, nullptr, kCFP, kCIN, 1);
    // 4) q_feat = CBL 128->128
    gemm3<<<dim3(kN / 64, 1, kB), 128>>>(whi + OFF_QM, wlo + OFF_QM, nf, qf,
                                         qm_b, qm_g, qm_be, nullptr, kC, kCFP, 1);
    // 5) v_feat via collapsed global-feature bias
    gbias_kernel<<<kB, kC>>>(fu_W, gfeat, gb);
    vfeat_kernel<<<dim3(kN / 256, kC, kB), 256>>>(fu_W, fu_b, fu_g, fu_be, gb, up_xyz, vf);
    // 6) fused Q/K/V projections
    qkv3<<<dim3(kN / 64, 3, kB), 128>>>(whi, wlo, qf, vf, Q, K, V);
    // 7) attention (tf32 tensor-core flash, no-max softmax)
    attn_mma<<<dim3(kN / 64, kB * kH), 128>>>(Q, K, V, O);
    // 8) proj + residual add (y = qf + Wp@O + bp)
    gemm3<<<dim3(kN / 64, 1, kB), 128>>>(whi + OFF_WP, wlo + OFF_WP, O, y,
                                         bp, nullptr, nullptr, qf, kC, kC, 0);
    // 9) out = CBL(y)
    gemm3<<<dim3(kN / 64, 1, kB), 128>>>(whi + OFF_OM, wlo + OFF_OM, y, (float*)d_out,
                                         om_b, om_g, om_be, nullptr, kC, kC, 1);
}

// round 10
// speedup vs baseline: 1.2640x; 1.2640x over previous
#include <cuda_runtime.h>
#include <cuda_bf16.h>
#include <math.h>

// ---------------- problem constants ----------------
constexpr int kB   = 8;
constexpr int kN   = 2048;
constexpr int kM   = 512;
constexpr int kCIN = 256;
constexpr int kCFP = 128;
constexpr int kC   = 128;   // C_OUT
constexpr int kCG  = 512;
constexpr int kH   = 8;
constexpr int kD   = 16;    // head dim

// ---------------- scratch (no allocation allowed) ----------------
__device__ float g_interp[kB * kCIN * kN];
__device__ float g_h1    [kB * kCIN * kN];
__device__ float g_nf    [kB * kCFP * kN];
__device__ float g_qf    [kB * kC   * kN];
__device__ float g_vf    [kB * kC   * kN];
__device__ float g_Q     [kB * kC   * kN];
__device__ float g_K     [kB * kC   * kN];
__device__ float g_V     [kB * kC   * kN];
__device__ float g_O     [kB * kC   * kN];
__device__ float g_y     [kB * kC   * kN];
__device__ float g_gb    [kB * kC];
__device__ int   g_idx   [kB * kN * 3];
__device__ float g_w     [kB * kN * 3];

// pre-split transposed packed weights: bf162 pairs along ic, layout [ic/2][oc]
constexpr int OFF_FP1 = 0;                 // 256x256
constexpr int OFF_FP2 = OFF_FP1 + 65536;   // 128x256
constexpr int OFF_QM  = OFF_FP2 + 32768;   // 128x128
constexpr int OFF_WQ  = OFF_QM  + 16384;
constexpr int OFF_WK  = OFF_WQ  + 16384;
constexpr int OFF_WV  = OFF_WK  + 16384;
constexpr int OFF_WP  = OFF_WV  + 16384;
constexpr int OFF_OM  = OFF_WP  + 16384;
constexpr int W_TOTAL = OFF_OM  + 16384;   // element count (fp32 source count)
__device__ __align__(16) __nv_bfloat16 g_whi16[W_TOTAL];
__device__ __align__(16) __nv_bfloat16 g_wlo16[W_TOTAL];

// ---------------- helpers ----------------
__device__ __forceinline__ float ex2(float x) {
    float y;
    asm("ex2.approx.f32 %0, %1;" : "=f"(y) : "f"(x));
    return y;
}
__device__ __forceinline__ unsigned cvt_tf32(float f) {
    unsigned u;
    asm("cvt.rna.tf32.f32 %0, %1;" : "=r"(u) : "f"(f));
    return u;
}
// tf32 m16n8k8 (attention only)
__device__ __forceinline__ void mma_tf32(float c[4], const unsigned a[4],
                                         unsigned b0, unsigned b1) {
    asm volatile(
        "mma.sync.aligned.m16n8k8.row.col.f32.tf32.tf32.f32 "
        "{%0,%1,%2,%3}, {%4,%5,%6,%7}, {%8,%9}, {%0,%1,%2,%3};"
        : "+f"(c[0]), "+f"(c[1]), "+f"(c[2]), "+f"(c[3])
        : "r"(a[0]), "r"(a[1]), "r"(a[2]), "r"(a[3]), "r"(b0), "r"(b1));
}
// bf16 m16n8k16 (GEMMs)
__device__ __forceinline__ void mma_bf16(float c[4], const unsigned a[4],
                                         unsigned b0, unsigned b1) {
    asm volatile(
        "mma.sync.aligned.m16n8k16.row.col.f32.bf16.bf16.f32 "
        "{%0,%1,%2,%3}, {%4,%5,%6,%7}, {%8,%9}, {%0,%1,%2,%3};"
        : "+f"(c[0]), "+f"(c[1]), "+f"(c[2]), "+f"(c[3])
        : "r"(a[0]), "r"(a[1]), "r"(a[2]), "r"(a[3]), "r"(b0), "r"(b1));
}
// split (a,b) pair -> packed bf162 hi and lo words
__device__ __forceinline__ void split_pair(float a, float b, unsigned& hi, unsigned& lo) {
    const __nv_bfloat16 ha = __float2bfloat16(a);
    const __nv_bfloat16 hb = __float2bfloat16(b);
    const __nv_bfloat16 la = __float2bfloat16(a - __bfloat162float(ha));
    const __nv_bfloat16 lb = __float2bfloat16(b - __bfloat162float(hb));
    const __nv_bfloat162 h2 = __halves2bfloat162(ha, hb);
    const __nv_bfloat162 l2 = __halves2bfloat162(la, lb);
    hi = *(const unsigned*)&h2;
    lo = *(const unsigned*)&l2;
}

// ---------------- weight pre-split (bf16 hi/lo, transposed, ic-paired) ----------------
struct PSArgs {
    const float* src[8];
    int off[8];
    int OC[8];
    int IC[8];
};
__global__ __launch_bounds__(256) void presplit_kernel(PSArgs a) {
    const int s  = blockIdx.y;
    const int OC = a.OC[s], IC = a.IC[s];
    const int n  = OC * IC;
    __nv_bfloat16* hi = g_whi16 + a.off[s];
    __nv_bfloat16* lo = g_wlo16 + a.off[s];
    for (int i = blockIdx.x * 256 + threadIdx.x; i < n; i += gridDim.x * 256) {
        const int oc = i / IC, ic = i - oc * IC;
        const float x = a.src[s][i];
        const __nv_bfloat16 h = __float2bfloat16(x);
        const __nv_bfloat16 l = __float2bfloat16(x - __bfloat162float(h));
        const size_t o = ((size_t)(ic >> 1) * OC + oc) * 2 + (ic & 1);
        hi[o] = h;
        lo[o] = l;
    }
}

// ---------------- three_nn ----------------
__global__ __launch_bounds__(128) void knn_kernel(
    const float* __restrict__ up_xyz, const float* __restrict__ xyz,
    int* __restrict__ idxo, float* __restrict__ wo)
{
    __shared__ float sx[kM * 3];
    const int b = blockIdx.y;
    for (int i = threadIdx.x; i < kM * 3; i += 128) sx[i] = xyz[b * kM * 3 + i];
    __syncthreads();

    const int n = blockIdx.x * 128 + threadIdx.x;
    const float px = up_xyz[(b * kN + n) * 3 + 0];
    const float py = up_xyz[(b * kN + n) * 3 + 1];
    const float pz = up_xyz[(b * kN + n) * 3 + 2];

    float d0 = 1e30f, d1 = 1e30f, d2 = 1e30f;
    int   i0 = 0,     i1 = 0,     i2 = 0;
    for (int m = 0; m < kM; m++) {
        float dx = sx[m * 3 + 0] - px;
        float dy = sx[m * 3 + 1] - py;
        float dz = sx[m * 3 + 2] - pz;
        float d  = dx * dx + dy * dy + dz * dz;
        if (d < d2) {
            if (d < d1) {
                if (d < d0) { d2 = d1; i2 = i1; d1 = d0; i1 = i0; d0 = d; i0 = m; }
                else        { d2 = d1; i2 = i1; d1 = d;  i1 = m; }
            } else          { d2 = d;  i2 = m; }
        }
    }
    d0 = fmaxf(d0, 1e-10f); d1 = fmaxf(d1, 1e-10f); d2 = fmaxf(d2, 1e-10f);
    float r0 = 1.0f / d0, r1 = 1.0f / d1, r2 = 1.0f / d2;
    float s  = r0 + r1 + r2;
    const int base = (b * kN + n) * 3;
    idxo[base] = i0; idxo[base + 1] = i1; idxo[base + 2] = i2;
    wo[base] = r0 / s; wo[base + 1] = r1 / s; wo[base + 2] = r2 / s;
}

// ---------------- inverse-distance interpolation ----------------
__global__ void interp_kernel(
    const float* __restrict__ feat, const int* __restrict__ idx3,
    const float* __restrict__ w3, float* __restrict__ out)
{
    const int b = blockIdx.z, c = blockIdx.y;
    const int n = blockIdx.x * 256 + threadIdx.x;
    const float* f = feat + ((size_t)b * kCIN + c) * kM;
    const int base = (b * kN + n) * 3;
    const int j0 = idx3[base], j1 = idx3[base + 1], j2 = idx3[base + 2];
    const float w0 = w3[base], w1 = w3[base + 1], w2 = w3[base + 2];
    out[((size_t)b * kCIN + c) * kN + n] = w0 * f[j0] + w1 * f[j1] + w2 * f[j2];
}

// ---------------- 3xBF16 GEMM: 128oc x 128n tile, 256 threads, k32/phase ----------------
// WhiP/WloP: packed bf162 [ic/2][OC] (as unsigned), pre-offset by oc0; ldw = OC.
__device__ __forceinline__ void gemmb_tile(
    const unsigned* __restrict__ WhiP, const unsigned* __restrict__ WloP,
    const float* __restrict__ Xb, float* __restrict__ Yb,
    int ldw, int IC, int n0,
    const float* bias, const float* gamma, const float* beta,
    const float* addB, int relu,
    unsigned (*Wsh)[136], unsigned (*Wsl)[136],
    unsigned (*Xsh)[136], unsigned (*Xsl)[136])
{
    const int tid  = threadIdx.x;
    const int w    = tid >> 5;
    const int lane = tid & 31;
    const int g    = lane >> 2;
    const int t    = lane & 3;
    const int ocw  = (w & 3) * 32;
    const int nw   = (w >> 2) * 64;

    const int lp = tid >> 4;            // loader pair-row 0..15
    const int lc = (tid & 15) * 8;      // loader col group (8 words)

    float c[2][8][4];
#pragma unroll
    for (int i = 0; i < 2; i++)
#pragma unroll
        for (int j = 0; j < 8; j++)
#pragma unroll
            for (int r = 0; r < 4; r++) c[i][j][r] = 0.0f;

    for (int k0 = 0; k0 < IC; k0 += 32) {
        // stage next slice in registers before the WAR sync
        const unsigned* wh = WhiP + (size_t)(k0 / 2 + lp) * ldw + lc;
        const unsigned* wl = WloP + (size_t)(k0 / 2 + lp) * ldw + lc;
        const uint4 wh0 = *(const uint4*)(wh);
        const uint4 wh1 = *(const uint4*)(wh + 4);
        const uint4 wl0 = *(const uint4*)(wl);
        const uint4 wl1 = *(const uint4*)(wl + 4);
        const float* xr0 = Xb + (size_t)(k0 + 2 * lp)     * kN + n0 + lc;
        const float* xr1 = Xb + (size_t)(k0 + 2 * lp + 1) * kN + n0 + lc;
        const float4 xa0 = *(const float4*)(xr0);
        const float4 xa1 = *(const float4*)(xr0 + 4);
        const float4 xb0 = *(const float4*)(xr1);
        const float4 xb1 = *(const float4*)(xr1 + 4);
        __syncthreads();
        *(uint4*)&Wsh[lp][lc]     = wh0;
        *(uint4*)&Wsh[lp][lc + 4] = wh1;
        *(uint4*)&Wsl[lp][lc]     = wl0;
        *(uint4*)&Wsl[lp][lc + 4] = wl1;
        split_pair(xa0.x, xb0.x, Xsh[lp][lc + 0], Xsl[lp][lc + 0]);
        split_pair(xa0.y, xb0.y, Xsh[lp][lc + 1], Xsl[lp][lc + 1]);
        split_pair(xa0.z, xb0.z, Xsh[lp][lc + 2], Xsl[lp][lc + 2]);
        split_pair(xa0.w, xb0.w, Xsh[lp][lc + 3], Xsl[lp][lc + 3]);
        split_pair(xa1.x, xb1.x, Xsh[lp][lc + 4], Xsl[lp][lc + 4]);
        split_pair(xa1.y, xb1.y, Xsh[lp][lc + 5], Xsl[lp][lc + 5]);
        split_pair(xa1.z, xb1.z, Xsh[lp][lc + 6], Xsl[lp][lc + 6]);
        split_pair(xa1.w, xb1.w, Xsh[lp][lc + 7], Xsl[lp][lc + 7]);
        __syncthreads();

#pragma unroll
        for (int kc = 0; kc < 2; kc++) {
            const int r0 = kc * 8 + t, r1 = kc * 8 + t + 4;
            unsigned ahi[2][4], alo[2][4];
#pragma unroll
            for (int i = 0; i < 2; i++) {
                const int oc = ocw + i * 16 + g;
                ahi[i][0] = Wsh[r0][oc];
                ahi[i][1] = Wsh[r0][oc + 8];
                ahi[i][2] = Wsh[r1][oc];
                ahi[i][3] = Wsh[r1][oc + 8];
                alo[i][0] = Wsl[r0][oc];
                alo[i][1] = Wsl[r0][oc + 8];
                alo[i][2] = Wsl[r1][oc];
                alo[i][3] = Wsl[r1][oc + 8];
            }
#pragma unroll
            for (int j = 0; j < 8; j++) {
                const int nc = nw + j * 8 + g;
                const unsigned bh0 = Xsh[r0][nc];
                const unsigned bh1 = Xsh[r1][nc];
                const unsigned bl0 = Xsl[r0][nc];
                const unsigned bl1 = Xsl[r1][nc];
#pragma unroll
                for (int i = 0; i < 2; i++) {
                    mma_bf16(c[i][j], ahi[i], bh0, bh1);
                    mma_bf16(c[i][j], alo[i], bh0, bh1);
                    mma_bf16(c[i][j], ahi[i], bl0, bl1);
                }
            }
        }
    }

    const float rs = rsqrtf(1.0f + 1e-5f);
#pragma unroll
    for (int i = 0; i < 2; i++) {
#pragma unroll
        for (int half = 0; half < 2; half++) {
            const int oc = ocw + i * 16 + g + half * 8;
            const float bi = bias  ? bias[oc]       : 0.0f;
            const float sc = gamma ? gamma[oc] * rs : 1.0f;
            const float bb = gamma ? beta[oc]       : 0.0f;
#pragma unroll
            for (int j = 0; j < 8; j++) {
                const int nc = n0 + nw + j * 8 + 2 * t;
                float v0 = fmaf(c[i][j][half * 2]     + bi, sc, bb);
                float v1 = fmaf(c[i][j][half * 2 + 1] + bi, sc, bb);
                if (addB) {
                    const float2 ad = *(const float2*)&addB[(size_t)oc * kN + nc];
                    v0 += ad.x; v1 += ad.y;
                }
                if (relu) { v0 = fmaxf(v0, 0.0f); v1 = fmaxf(v1, 0.0f); }
                *(float2*)&Yb[(size_t)oc * kN + nc] = make_float2(v0, v1);
            }
        }
    }
}

__global__ __launch_bounds__(256, 2) void gemmb(
    int woff, const float* __restrict__ X, float* __restrict__ Y,
    const float* __restrict__ bias, const float* __restrict__ gamma,
    const float* __restrict__ beta, const float* __restrict__ add,
    int OC, int IC, int relu)
{
    __shared__ unsigned Wsh[16][136];
    __shared__ unsigned Wsl[16][136];
    __shared__ unsigned Xsh[16][136];
    __shared__ unsigned Xsl[16][136];
    const int b   = blockIdx.z;
    const int n0  = blockIdx.x * 128;
    const int oc0 = blockIdx.y * 128;
    gemmb_tile((const unsigned*)(g_whi16 + woff) + oc0,
               (const unsigned*)(g_wlo16 + woff) + oc0,
               X + (size_t)b * IC * kN,
               Y + ((size_t)b * OC + oc0) * kN,
               OC, IC, n0,
               bias  ? bias  + oc0 : nullptr,
               gamma ? gamma + oc0 : nullptr,
               beta  ? beta  + oc0 : nullptr,
               add   ? add + ((size_t)b * OC + oc0) * kN : nullptr,
               relu, Wsh, Wsl, Xsh, Xsl);
}

__global__ __launch_bounds__(256, 2) void qkvb(
    const float* __restrict__ qf, const float* __restrict__ vf,
    float* __restrict__ Q, float* __restrict__ K, float* __restrict__ V)
{
    __shared__ unsigned Wsh[16][136];
    __shared__ unsigned Wsl[16][136];
    __shared__ unsigned Xsh[16][136];
    __shared__ unsigned Xsl[16][136];
    const int b = blockIdx.z;
    const int y = blockIdx.y;
    const int off = (y == 0) ? OFF_WQ : (y == 1) ? OFF_WK : OFF_WV;
    const float* X = ((y == 0) ? qf : vf) + (size_t)b * kC * kN;
    float*       Y = ((y == 0) ? Q : (y == 1) ? K : V) + (size_t)b * kC * kN;
    gemmb_tile((const unsigned*)(g_whi16 + off),
               (const unsigned*)(g_wlo16 + off),
               X, Y, kC, kC, blockIdx.x * 128,
               nullptr, nullptr, nullptr, nullptr, 0, Wsh, Wsl, Xsh, Xsl);
}

// ---------------- v_feat helpers ----------------
__global__ void gbias_kernel(const float* __restrict__ fuW, const float* __restrict__ gf,
                             float* __restrict__ gb)
{
    const int b = blockIdx.x, c = threadIdx.x;
    const float* w = fuW + (size_t)c * (3 + kCG) + 3;
    const float* g = gf + b * kCG;
    float s = 0.0f;
    for (int j = 0; j < kCG; j++) s = fmaf(w[j], g[j], s);
    gb[b * kC + c] = s;
}

__global__ void vfeat_kernel(
    const float* __restrict__ fuW, const float* __restrict__ fub,
    const float* __restrict__ fug, const float* __restrict__ fube,
    const float* __restrict__ gb, const float* __restrict__ up_xyz,
    float* __restrict__ vf)
{
    const int b = blockIdx.z, c = blockIdx.y;
    const int n = blockIdx.x * 256 + threadIdx.x;
    const float w0 = fuW[c * (3 + kCG) + 0];
    const float w1 = fuW[c * (3 + kCG) + 1];
    const float w2 = fuW[c * (3 + kCG) + 2];
    const float x = up_xyz[(b * kN + n) * 3 + 0];
    const float y = up_xyz[(b * kN + n) * 3 + 1];
    const float z = up_xyz[(b * kN + n) * 3 + 2];
    float a = gb[b * kC + c] + fub[c] + w0 * x + w1 * y + w2 * z;
    const float rs = rsqrtf(1.0f + 1e-5f);
    a = fmaf(a, fug[c] * rs, fube[c]);
    vf[((size_t)b * kC + c) * kN + n] = fmaxf(a, 0.0f);
}

// ---------------- tf32 MMA flash attention (no max tracking) ----------------
__global__ __launch_bounds__(128) void attn_mma(
    const float* __restrict__ Q, const float* __restrict__ K,
    const float* __restrict__ V, float* __restrict__ O)
{
    __shared__ float Ks[kD][72];
    __shared__ float Vs[kD][72];
    const int bh   = blockIdx.y;
    const int tid  = threadIdx.x;
    const int warp = tid >> 5;
    const int lane = tid & 31;
    const int g    = lane >> 2;
    const int t    = lane & 3;

    const float* Qb = Q + (size_t)bh * kD * kN;
    const float* Kb = K + (size_t)bh * kD * kN;
    const float* Vb = V + (size_t)bh * kD * kN;
    float*       Ob = O + (size_t)bh * kD * kN;

    const float ALPHA = 0.25f * 1.44269504088896340736f;
    const int q0 = blockIdx.x * 64 + warp * 16 + g;

    unsigned aq[2][4];
#pragma unroll
    for (int ks = 0; ks < 2; ks++) {
        aq[ks][0] = cvt_tf32(Qb[(size_t)(ks * 8 + t)     * kN + q0]     * ALPHA);
        aq[ks][1] = cvt_tf32(Qb[(size_t)(ks * 8 + t)     * kN + q0 + 8] * ALPHA);
        aq[ks][2] = cvt_tf32(Qb[(size_t)(ks * 8 + t + 4) * kN + q0]     * ALPHA);
        aq[ks][3] = cvt_tf32(Qb[(size_t)(ks * 8 + t + 4) * kN + q0 + 8] * ALPHA);
    }

    float o0[4] = {0.f, 0.f, 0.f, 0.f};
    float o1[4] = {0.f, 0.f, 0.f, 0.f};
    float l0 = 0.f, l1 = 0.f;

    const int ld_d = tid >> 3;
    const int ld_k = (tid & 7) * 8;

    for (int kt = 0; kt < kN / 64; kt++) {
        const int k0 = kt * 64;
        __syncthreads();
        *(float4*)&Ks[ld_d][ld_k]     = *(const float4*)&Kb[(size_t)ld_d * kN + k0 + ld_k];
        *(float4*)&Ks[ld_d][ld_k + 4] = *(const float4*)&Kb[(size_t)ld_d * kN + k0 + ld_k + 4];
        *(float4*)&Vs[ld_d][ld_k]     = *(const float4*)&Vb[(size_t)ld_d * kN + k0 + ld_k];
        *(float4*)&Vs[ld_d][ld_k + 4] = *(const float4*)&Vb[(size_t)ld_d * kN + k0 + ld_k + 4];
        __syncthreads();

#pragma unroll
        for (int nt = 0; nt < 8; nt++) {
            float c[4] = {0.f, 0.f, 0.f, 0.f};
#pragma unroll
            for (int ks = 0; ks < 2; ks++) {
                const unsigned kb0 = __float_as_uint(Ks[ks * 8 + t][nt * 8 + g]);
                const unsigned kb1 = __float_as_uint(Ks[ks * 8 + t + 4][nt * 8 + g]);
                mma_tf32(c, aq[ks], kb0, kb1);
            }
            const float p0 = ex2(c[0]);
            const float p1 = ex2(c[1]);
            const float p2 = ex2(c[2]);
            const float p3 = ex2(c[3]);
            l0 += p0 + p1;
            l1 += p2 + p3;
            const unsigned pa[4] = {__float_as_uint(p0), __float_as_uint(p2),
                                    __float_as_uint(p1), __float_as_uint(p3)};
#pragma unroll
            for (int dt = 0; dt < 2; dt++) {
                const float2 bv = *(const float2*)&Vs[dt * 8 + g][nt * 8 + 2 * t];
                mma_tf32(dt ? o1 : o0, pa,
                         __float_as_uint(bv.x), __float_as_uint(bv.y));
            }
        }
    }

    l0 += __shfl_xor_sync(0xFFFFFFFFu, l0, 1);
    l0 += __shfl_xor_sync(0xFFFFFFFFu, l0, 2);
    l1 += __shfl_xor_sync(0xFFFFFFFFu, l1, 1);
    l1 += __shfl_xor_sync(0xFFFFFFFFu, l1, 2);
    const float inv0 = 1.0f / l0;
    const float inv1 = 1.0f / l1;

#pragma unroll
    for (int dt = 0; dt < 2; dt++) {
        const float* o = dt ? o1 : o0;
        const int d = dt * 8 + 2 * t;
        Ob[(size_t)d       * kN + q0]     = o[0] * inv0;
        Ob[(size_t)(d + 1) * kN + q0]     = o[1] * inv0;
        Ob[(size_t)d       * kN + q0 + 8] = o[2] * inv1;
        Ob[(size_t)(d + 1) * kN + q0 + 8] = o[3] * inv1;
    }
}

// ---------------- launch ----------------
extern "C" void kernel_launch(void* const* d_in, const int* in_sizes, int n_in,
                              void* d_out, int out_size)
{
    const float* up_xyz   = (const float*)d_in[0];
    const float* xyz      = (const float*)d_in[1];
    const float* features = (const float*)d_in[2];
    const float* gfeat    = (const float*)d_in[3];
    const float* fp1_W = (const float*)d_in[4];
    const float* fp1_b = (const float*)d_in[5];
    const float* fp1_g = (const float*)d_in[6];
    const float* fp1_be= (const float*)d_in[7];
    const float* fp2_W = (const float*)d_in[8];
    const float* fp2_b = (const float*)d_in[9];
    const float* fp2_g = (const float*)d_in[10];
    const float* fp2_be= (const float*)d_in[11];
    const float* qm_W  = (const float*)d_in[12];
    const float* qm_b  = (const float*)d_in[13];
    const float* qm_g  = (const float*)d_in[14];
    const float* qm_be = (const float*)d_in[15];
    const float* fu_W  = (const float*)d_in[16];
    const float* fu_b  = (const float*)d_in[17];
    const float* fu_g  = (const float*)d_in[18];
    const float* fu_be = (const float*)d_in[19];
    const float* Wq    = (const float*)d_in[20];
    const float* Wk    = (const float*)d_in[21];
    const float* Wv    = (const float*)d_in[22];
    const float* Wp    = (const float*)d_in[23];
    const float* bp    = (const float*)d_in[24];
    const float* om_W  = (const float*)d_in[25];
    const float* om_b  = (const float*)d_in[26];
    const float* om_g  = (const float*)d_in[27];
    const float* om_be = (const float*)d_in[28];

    float *interp, *h1, *nf, *qf, *vf, *Q, *K, *V, *O, *y, *gb, *w;
    int* idx;
    cudaGetSymbolAddress((void**)&interp, g_interp);
    cudaGetSymbolAddress((void**)&h1,     g_h1);
    cudaGetSymbolAddress((void**)&nf,     g_nf);
    cudaGetSymbolAddress((void**)&qf,     g_qf);
    cudaGetSymbolAddress((void**)&vf,     g_vf);
    cudaGetSymbolAddress((void**)&Q,      g_Q);
    cudaGetSymbolAddress((void**)&K,      g_K);
    cudaGetSymbolAddress((void**)&V,      g_V);
    cudaGetSymbolAddress((void**)&O,      g_O);
    cudaGetSymbolAddress((void**)&y,      g_y);
    cudaGetSymbolAddress((void**)&gb,     g_gb);
    cudaGetSymbolAddress((void**)&idx,    g_idx);
    cudaGetSymbolAddress((void**)&w,      g_w);

    // 0) pre-split all weights into transposed, ic-paired bf16 hi/lo
    PSArgs ps;
    ps.src[0] = fp1_W; ps.off[0] = OFF_FP1; ps.OC[0] = kCIN; ps.IC[0] = kCIN;
    ps.src[1] = fp2_W; ps.off[1] = OFF_FP2; ps.OC[1] = kCFP; ps.IC[1] = kCIN;
    ps.src[2] = qm_W;  ps.off[2] = OFF_QM;  ps.OC[2] = kC;   ps.IC[2] = kCFP;
    ps.src[3] = Wq;    ps.off[3] = OFF_WQ;  ps.OC[3] = kC;   ps.IC[3] = kC;
    ps.src[4] = Wk;    ps.off[4] = OFF_WK;  ps.OC[4] = kC;   ps.IC[4] = kC;
    ps.src[5] = Wv;    ps.off[5] = OFF_WV;  ps.OC[5] = kC;   ps.IC[5] = kC;
    ps.src[6] = Wp;    ps.off[6] = OFF_WP;  ps.OC[6] = kC;   ps.IC[6] = kC;
    ps.src[7] = om_W;  ps.off[7] = OFF_OM;  ps.OC[7] = kC;   ps.IC[7] = kC;
    presplit_kernel<<<dim3(32, 8), 256>>>(ps);

    // 1) three_nn + weights
    knn_kernel<<<dim3(kN / 128, kB), 128>>>(up_xyz, xyz, idx, w);
    // 2) inverse-distance interpolation -> (B,256,N)
    interp_kernel<<<dim3(kN / 256, kCIN, kB), 256>>>(features, idx, w, interp);
    // 3) fp mlp: CBL 256->256, CBL 256->128  (3xBF16 tensor GEMM)
    gemmb<<<dim3(kN / 128, kCIN / 128, kB), 256>>>(OFF_FP1, interp, h1,
                                                   fp1_b, fp1_g, fp1_be, nullptr, kCIN, kCIN, 1);
    gemmb<<<dim3(kN / 128, 1, kB), 256>>>(OFF_FP2, h1, nf,
                                          fp2_b, fp2_g, fp2_be, nullptr, kCFP, kCIN, 1);
    // 4) q_feat = CBL 128->128
    gemmb<<<dim3(kN / 128, 1, kB), 256>>>(OFF_QM, nf, qf,
                                          qm_b, qm_g, qm_be, nullptr, kC, kCFP, 1);
    // 5) v_feat via collapsed global-feature bias
    gbias_kernel<<<kB, kC>>>(fu_W, gfeat, gb);
    vfeat_kernel<<<dim3(kN / 256, kC, kB), 256>>>(fu_W, fu_b, fu_g, fu_be, gb, up_xyz, vf);
    // 6) fused Q/K/V projections
    qkvb<<<dim3(kN / 128, 3, kB), 256>>>(qf, vf, Q, K, V);
    // 7) attention (tf32 tensor-core flash, no-max softmax)
    attn_mma<<<dim3(kN / 64, kB * kH), 128>>>(Q, K, V, O);
    // 8) proj + residual add (y = qf + Wp@O + bp)
    gemmb<<<dim3(kN / 128, 1, kB), 256>>>(OFF_WP, O, y,
                                          bp, nullptr, nullptr, qf, kC, kC, 0);
    // 9) out = CBL(y)
    gemmb<<<dim3(kN / 128, 1, kB), 256>>>(OFF_OM, y, (float*)d_out,
                                          om_b, om_g, om_be, nullptr, kC, kC, 1);
}

// round 11
// speedup vs baseline: 1.2849x; 1.0166x over previous
#include <cuda_runtime.h>
#include <cuda_bf16.h>
#include <math.h>

// ---------------- problem constants ----------------
constexpr int kB   = 8;
constexpr int kN   = 2048;
constexpr int kM   = 512;
constexpr int kCIN = 256;
constexpr int kCFP = 128;
constexpr int kC   = 128;   // C_OUT
constexpr int kCG  = 512;
constexpr int kH   = 8;
constexpr int kD   = 16;    // head dim

// ---------------- scratch (no allocation allowed) ----------------
__device__ float g_interp[kB * kCIN * kN];
__device__ float g_h1    [kB * kCIN * kN];
__device__ float g_nf    [kB * kCFP * kN];
__device__ float g_qf    [kB * kC   * kN];
__device__ float g_vf    [kB * kC   * kN];
__device__ float g_Q     [kB * kC   * kN];
__device__ float g_K     [kB * kC   * kN];
__device__ float g_V     [kB * kC   * kN];
__device__ float g_O     [kB * kC   * kN];
__device__ float g_y     [kB * kC   * kN];
__device__ float g_gb    [kB * kC];
__device__ int   g_idx   [kB * kN * 3];
__device__ float g_w     [kB * kN * 3];

// pre-split transposed packed weights: bf162 pairs along ic, layout [ic/2][oc]
constexpr int OFF_FP1 = 0;                 // 256x256
constexpr int OFF_FP2 = OFF_FP1 + 65536;   // 128x256
constexpr int OFF_QM  = OFF_FP2 + 32768;   // 128x128
constexpr int OFF_WQ  = OFF_QM  + 16384;
constexpr int OFF_WK  = OFF_WQ  + 16384;
constexpr int OFF_WV  = OFF_WK  + 16384;
constexpr int OFF_WP  = OFF_WV  + 16384;
constexpr int OFF_OM  = OFF_WP  + 16384;
constexpr int W_TOTAL = OFF_OM  + 16384;
__device__ __align__(16) __nv_bfloat16 g_whi16[W_TOTAL];
__device__ __align__(16) __nv_bfloat16 g_wlo16[W_TOTAL];

// ---------------- helpers ----------------
__device__ __forceinline__ float ex2(float x) {
    float y;
    asm("ex2.approx.f32 %0, %1;" : "=f"(y) : "f"(x));
    return y;
}
__device__ __forceinline__ unsigned cvt_tf32(float f) {
    unsigned u;
    asm("cvt.rna.tf32.f32 %0, %1;" : "=r"(u) : "f"(f));
    return u;
}
__device__ __forceinline__ void mma_tf32(float c[4], const unsigned a[4],
                                         unsigned b0, unsigned b1) {
    asm volatile(
        "mma.sync.aligned.m16n8k8.row.col.f32.tf32.tf32.f32 "
        "{%0,%1,%2,%3}, {%4,%5,%6,%7}, {%8,%9}, {%0,%1,%2,%3};"
        : "+f"(c[0]), "+f"(c[1]), "+f"(c[2]), "+f"(c[3])
        : "r"(a[0]), "r"(a[1]), "r"(a[2]), "r"(a[3]), "r"(b0), "r"(b1));
}
__device__ __forceinline__ void mma_bf16(float c[4], const unsigned a[4],
                                         unsigned b0, unsigned b1) {
    asm volatile(
        "mma.sync.aligned.m16n8k16.row.col.f32.bf16.bf16.f32 "
        "{%0,%1,%2,%3}, {%4,%5,%6,%7}, {%8,%9}, {%0,%1,%2,%3};"
        : "+f"(c[0]), "+f"(c[1]), "+f"(c[2]), "+f"(c[3])
        : "r"(a[0]), "r"(a[1]), "r"(a[2]), "r"(a[3]), "r"(b0), "r"(b1));
}
__device__ __forceinline__ void split_pair(float a, float b, unsigned& hi, unsigned& lo) {
    const __nv_bfloat16 ha = __float2bfloat16(a);
    const __nv_bfloat16 hb = __float2bfloat16(b);
    const __nv_bfloat16 la = __float2bfloat16(a - __bfloat162float(ha));
    const __nv_bfloat16 lb = __float2bfloat16(b - __bfloat162float(hb));
    const __nv_bfloat162 h2 = __halves2bfloat162(ha, hb);
    const __nv_bfloat162 l2 = __halves2bfloat162(la, lb);
    hi = *(const unsigned*)&h2;
    lo = *(const unsigned*)&l2;
}

// ---------------- weight pre-split ----------------
struct PSArgs {
    const float* src[8];
    int off[8];
    int OC[8];
    int IC[8];
};
__global__ __launch_bounds__(256) void presplit_kernel(PSArgs a) {
    const int s  = blockIdx.y;
    const int OC = a.OC[s], IC = a.IC[s];
    const int n  = OC * IC;
    __nv_bfloat16* hi = g_whi16 + a.off[s];
    __nv_bfloat16* lo = g_wlo16 + a.off[s];
    for (int i = blockIdx.x * 256 + threadIdx.x; i < n; i += gridDim.x * 256) {
        const int oc = i / IC, ic = i - oc * IC;
        const float x = a.src[s][i];
        const __nv_bfloat16 h = __float2bfloat16(x);
        const __nv_bfloat16 l = __float2bfloat16(x - __bfloat162float(h));
        const size_t o = ((size_t)(ic >> 1) * OC + oc) * 2 + (ic & 1);
        hi[o] = h;
        lo[o] = l;
    }
}

// ---------------- three_nn ----------------
__global__ __launch_bounds__(128) void knn_kernel(
    const float* __restrict__ up_xyz, const float* __restrict__ xyz,
    int* __restrict__ idxo, float* __restrict__ wo)
{
    __shared__ float sx[kM * 3];
    const int b = blockIdx.y;
    for (int i = threadIdx.x; i < kM * 3; i += 128) sx[i] = xyz[b * kM * 3 + i];
    __syncthreads();

    const int n = blockIdx.x * 128 + threadIdx.x;
    const float px = up_xyz[(b * kN + n) * 3 + 0];
    const float py = up_xyz[(b * kN + n) * 3 + 1];
    const float pz = up_xyz[(b * kN + n) * 3 + 2];

    float d0 = 1e30f, d1 = 1e30f, d2 = 1e30f;
    int   i0 = 0,     i1 = 0,     i2 = 0;
    for (int m = 0; m < kM; m++) {
        float dx = sx[m * 3 + 0] - px;
        float dy = sx[m * 3 + 1] - py;
        float dz = sx[m * 3 + 2] - pz;
        float d  = dx * dx + dy * dy + dz * dz;
        if (d < d2) {
            if (d < d1) {
                if (d < d0) { d2 = d1; i2 = i1; d1 = d0; i1 = i0; d0 = d; i0 = m; }
                else        { d2 = d1; i2 = i1; d1 = d;  i1 = m; }
            } else          { d2 = d;  i2 = m; }
        }
    }
    d0 = fmaxf(d0, 1e-10f); d1 = fmaxf(d1, 1e-10f); d2 = fmaxf(d2, 1e-10f);
    float r0 = 1.0f / d0, r1 = 1.0f / d1, r2 = 1.0f / d2;
    float s  = r0 + r1 + r2;
    const int base = (b * kN + n) * 3;
    idxo[base] = i0; idxo[base + 1] = i1; idxo[base + 2] = i2;
    wo[base] = r0 / s; wo[base + 1] = r1 / s; wo[base + 2] = r2 / s;
}

// ---------------- interpolation with smem-cached feature row ----------------
__global__ __launch_bounds__(256) void interp_kernel(
    const float* __restrict__ feat, const int* __restrict__ idx3,
    const float* __restrict__ w3, float* __restrict__ out)
{
    __shared__ float fs[kM];
    const int b = blockIdx.z, c = blockIdx.y;
    const float* f = feat + ((size_t)b * kCIN + c) * kM;
    fs[threadIdx.x]       = f[threadIdx.x];
    fs[threadIdx.x + 256] = f[threadIdx.x + 256];
    __syncthreads();

    const int n = blockIdx.x * 256 + threadIdx.x;
    const int base = (b * kN + n) * 3;
    const int j0 = idx3[base], j1 = idx3[base + 1], j2 = idx3[base + 2];
    const float w0 = w3[base], w1 = w3[base + 1], w2 = w3[base + 2];
    out[((size_t)b * kCIN + c) * kN + n] = w0 * fs[j0] + w1 * fs[j1] + w2 * fs[j2];
}

// ---------------- 3xBF16 GEMM: 128oc x 64n tile, 256 threads (4oc x 2n warps) ----------------
__device__ __forceinline__ void gemmb_tile(
    const unsigned* __restrict__ WhiP, const unsigned* __restrict__ WloP,
    const float* __restrict__ Xb, float* __restrict__ Yb,
    int ldw, int IC, int n0,
    const float* bias, const float* gamma, const float* beta,
    const float* addB, int relu,
    unsigned (*Wsh)[136], unsigned (*Wsl)[136],
    unsigned (*Xsh)[72], unsigned (*Xsl)[72])
{
    const int tid  = threadIdx.x;
    const int w    = tid >> 5;
    const int lane = tid & 31;
    const int g    = lane >> 2;
    const int t    = lane & 3;
    const int ocw  = (w & 3) * 32;
    const int nw   = (w >> 2) * 32;

    const int lp = tid >> 4;            // W loader pair-row 0..15
    const int lc = (tid & 15) * 8;      // W loader col group (8 words)
    const int xp = tid >> 4;            // X loader pair-row 0..15
    const int xc = (tid & 15) * 4;      // X loader col group (4 words)

    float c[2][4][4];
#pragma unroll
    for (int i = 0; i < 2; i++)
#pragma unroll
        for (int j = 0; j < 4; j++)
#pragma unroll
            for (int r = 0; r < 4; r++) c[i][j][r] = 0.0f;

    for (int k0 = 0; k0 < IC; k0 += 32) {
        // stage next slice in registers before the WAR sync
        const unsigned* wh = WhiP + (size_t)(k0 / 2 + lp) * ldw + lc;
        const unsigned* wl = WloP + (size_t)(k0 / 2 + lp) * ldw + lc;
        const uint4 wh0 = *(const uint4*)(wh);
        const uint4 wh1 = *(const uint4*)(wh + 4);
        const uint4 wl0 = *(const uint4*)(wl);
        const uint4 wl1 = *(const uint4*)(wl + 4);
        const float* xr0 = Xb + (size_t)(k0 + 2 * xp)     * kN + n0 + xc;
        const float* xr1 = Xb + (size_t)(k0 + 2 * xp + 1) * kN + n0 + xc;
        const float4 xa = *(const float4*)(xr0);
        const float4 xb = *(const float4*)(xr1);
        __syncthreads();
        *(uint4*)&Wsh[lp][lc]     = wh0;
        *(uint4*)&Wsh[lp][lc + 4] = wh1;
        *(uint4*)&Wsl[lp][lc]     = wl0;
        *(uint4*)&Wsl[lp][lc + 4] = wl1;
        split_pair(xa.x, xb.x, Xsh[xp][xc + 0], Xsl[xp][xc + 0]);
        split_pair(xa.y, xb.y, Xsh[xp][xc + 1], Xsl[xp][xc + 1]);
        split_pair(xa.z, xb.z, Xsh[xp][xc + 2], Xsl[xp][xc + 2]);
        split_pair(xa.w, xb.w, Xsh[xp][xc + 3], Xsl[xp][xc + 3]);
        __syncthreads();

#pragma unroll
        for (int kc = 0; kc < 2; kc++) {
            const int r0 = kc * 8 + t, r1 = kc * 8 + t + 4;
            unsigned ahi[2][4], alo[2][4];
#pragma unroll
            for (int i = 0; i < 2; i++) {
                const int oc = ocw + i * 16 + g;
                ahi[i][0] = Wsh[r0][oc];
                ahi[i][1] = Wsh[r0][oc + 8];
                ahi[i][2] = Wsh[r1][oc];
                ahi[i][3] = Wsh[r1][oc + 8];
                alo[i][0] = Wsl[r0][oc];
                alo[i][1] = Wsl[r0][oc + 8];
                alo[i][2] = Wsl[r1][oc];
                alo[i][3] = Wsl[r1][oc + 8];
            }
#pragma unroll
            for (int j = 0; j < 4; j++) {
                const int nc = nw + j * 8 + g;
                const unsigned bh0 = Xsh[r0][nc];
                const unsigned bh1 = Xsh[r1][nc];
                const unsigned bl0 = Xsl[r0][nc];
                const unsigned bl1 = Xsl[r1][nc];
#pragma unroll
                for (int i = 0; i < 2; i++) {
                    mma_bf16(c[i][j], ahi[i], bh0, bh1);
                    mma_bf16(c[i][j], alo[i], bh0, bh1);
                    mma_bf16(c[i][j], ahi[i], bl0, bl1);
                }
            }
        }
    }

    const float rs = rsqrtf(1.0f + 1e-5f);
#pragma unroll
    for (int i = 0; i < 2; i++) {
#pragma unroll
        for (int half = 0; half < 2; half++) {
            const int oc = ocw + i * 16 + g + half * 8;
            const float bi = bias  ? bias[oc]       : 0.0f;
            const float sc = gamma ? gamma[oc] * rs : 1.0f;
            const float bb = gamma ? beta[oc]       : 0.0f;
#pragma unroll
            for (int j = 0; j < 4; j++) {
                const int nc = n0 + nw + j * 8 + 2 * t;
                float v0 = fmaf(c[i][j][half * 2]     + bi, sc, bb);
                float v1 = fmaf(c[i][j][half * 2 + 1] + bi, sc, bb);
                if (addB) {
                    const float2 ad = *(const float2*)&addB[(size_t)oc * kN + nc];
                    v0 += ad.x; v1 += ad.y;
                }
                if (relu) { v0 = fmaxf(v0, 0.0f); v1 = fmaxf(v1, 0.0f); }
                *(float2*)&Yb[(size_t)oc * kN + nc] = make_float2(v0, v1);
            }
        }
    }
}

__global__ __launch_bounds__(256, 2) void gemmb(
    int woff, const float* __restrict__ X, float* __restrict__ Y,
    const float* __restrict__ bias, const float* __restrict__ gamma,
    const float* __restrict__ beta, const float* __restrict__ add,
    int OC, int IC, int relu)
{
    __shared__ unsigned Wsh[16][136];
    __shared__ unsigned Wsl[16][136];
    __shared__ unsigned Xsh[16][72];
    __shared__ unsigned Xsl[16][72];
    const int b   = blockIdx.z;
    const int n0  = blockIdx.x * 64;
    const int oc0 = blockIdx.y * 128;
    gemmb_tile((const unsigned*)(g_whi16 + woff) + oc0,
               (const unsigned*)(g_wlo16 + woff) + oc0,
               X + (size_t)b * IC * kN,
               Y + ((size_t)b * OC + oc0) * kN,
               OC, IC, n0,
               bias  ? bias  + oc0 : nullptr,
               gamma ? gamma + oc0 : nullptr,
               beta  ? beta  + oc0 : nullptr,
               add   ? add + ((size_t)b * OC + oc0) * kN : nullptr,
               relu, Wsh, Wsl, Xsh, Xsl);
}

__global__ __launch_bounds__(256, 2) void qkvb(
    const float* __restrict__ qf, const float* __restrict__ vf,
    float* __restrict__ Q, float* __restrict__ K, float* __restrict__ V)
{
    __shared__ unsigned Wsh[16][136];
    __shared__ unsigned Wsl[16][136];
    __shared__ unsigned Xsh[16][72];
    __shared__ unsigned Xsl[16][72];
    const int b = blockIdx.z;
    const int y = blockIdx.y;
    const int off = (y == 0) ? OFF_WQ : (y == 1) ? OFF_WK : OFF_WV;
    const float* X = ((y == 0) ? qf : vf) + (size_t)b * kC * kN;
    float*       Y = ((y == 0) ? Q : (y == 1) ? K : V) + (size_t)b * kC * kN;
    gemmb_tile((const unsigned*)(g_whi16 + off),
               (const unsigned*)(g_wlo16 + off),
               X, Y, kC, kC, blockIdx.x * 64,
               nullptr, nullptr, nullptr, nullptr, 0, Wsh, Wsl, Xsh, Xsl);
}

// ---------------- v_feat helpers ----------------
__global__ void gbias_kernel(const float* __restrict__ fuW, const float* __restrict__ gf,
                             float* __restrict__ gb)
{
    const int b = blockIdx.x, c = threadIdx.x;
    const float* w = fuW + (size_t)c * (3 + kCG) + 3;
    const float* g = gf + b * kCG;
    float s = 0.0f;
    for (int j = 0; j < kCG; j++) s = fmaf(w[j], g[j], s);
    gb[b * kC + c] = s;
}

__global__ void vfeat_kernel(
    const float* __restrict__ fuW, const float* __restrict__ fub,
    const float* __restrict__ fug, const float* __restrict__ fube,
    const float* __restrict__ gb, const float* __restrict__ up_xyz,
    float* __restrict__ vf)
{
    const int b = blockIdx.z, c = blockIdx.y;
    const int n = blockIdx.x * 256 + threadIdx.x;
    const float w0 = fuW[c * (3 + kCG) + 0];
    const float w1 = fuW[c * (3 + kCG) + 1];
    const float w2 = fuW[c * (3 + kCG) + 2];
    const float x = up_xyz[(b * kN + n) * 3 + 0];
    const float y = up_xyz[(b * kN + n) * 3 + 1];
    const float z = up_xyz[(b * kN + n) * 3 + 2];
    float a = gb[b * kC + c] + fub[c] + w0 * x + w1 * y + w2 * z;
    const float rs = rsqrtf(1.0f + 1e-5f);
    a = fmaf(a, fug[c] * rs, fube[c]);
    vf[((size_t)b * kC + c) * kN + n] = fmaxf(a, 0.0f);
}

// ---------------- tf32 MMA flash attention (no max tracking) ----------------
__global__ __launch_bounds__(128) void attn_mma(
    const float* __restrict__ Q, const float* __restrict__ K,
    const float* __restrict__ V, float* __restrict__ O)
{
    __shared__ float Ks[kD][72];
    __shared__ float Vs[kD][72];
    const int bh   = blockIdx.y;
    const int tid  = threadIdx.x;
    const int warp = tid >> 5;
    const int lane = tid & 31;
    const int g    = lane >> 2;
    const int t    = lane & 3;

    const float* Qb = Q + (size_t)bh * kD * kN;
    const float* Kb = K + (size_t)bh * kD * kN;
    const float* Vb = V + (size_t)bh * kD * kN;
    float*       Ob = O + (size_t)bh * kD * kN;

    const float ALPHA = 0.25f * 1.44269504088896340736f;
    const int q0 = blockIdx.x * 64 + warp * 16 + g;

    unsigned aq[2][4];
#pragma unroll
    for (int ks = 0; ks < 2; ks++) {
        aq[ks][0] = cvt_tf32(Qb[(size_t)(ks * 8 + t)     * kN + q0]     * ALPHA);
        aq[ks][1] = cvt_tf32(Qb[(size_t)(ks * 8 + t)     * kN + q0 + 8] * ALPHA);
        aq[ks][2] = cvt_tf32(Qb[(size_t)(ks * 8 + t + 4) * kN + q0]     * ALPHA);
        aq[ks][3] = cvt_tf32(Qb[(size_t)(ks * 8 + t + 4) * kN + q0 + 8] * ALPHA);
    }

    float o0[4] = {0.f, 0.f, 0.f, 0.f};
    float o1[4] = {0.f, 0.f, 0.f, 0.f};
    float l0 = 0.f, l1 = 0.f;

    const int ld_d = tid >> 3;
    const int ld_k = (tid & 7) * 8;

    for (int kt = 0; kt < kN / 64; kt++) {
        const int k0 = kt * 64;
        __syncthreads();
        *(float4*)&Ks[ld_d][ld_k]     = *(const float4*)&Kb[(size_t)ld_d * kN + k0 + ld_k];
        *(float4*)&Ks[ld_d][ld_k + 4] = *(const float4*)&Kb[(size_t)ld_d * kN + k0 + ld_k + 4];
        *(float4*)&Vs[ld_d][ld_k]     = *(const float4*)&Vb[(size_t)ld_d * kN + k0 + ld_k];
        *(float4*)&Vs[ld_d][ld_k + 4] = *(const float4*)&Vb[(size_t)ld_d * kN + k0 + ld_k + 4];
        __syncthreads();

#pragma unroll
        for (int nt = 0; nt < 8; nt++) {
            float c[4] = {0.f, 0.f, 0.f, 0.f};
#pragma unroll
            for (int ks = 0; ks < 2; ks++) {
                const unsigned kb0 = __float_as_uint(Ks[ks * 8 + t][nt * 8 + g]);
                const unsigned kb1 = __float_as_uint(Ks[ks * 8 + t + 4][nt * 8 + g]);
                mma_tf32(c, aq[ks], kb0, kb1);
            }
            const float p0 = ex2(c[0]);
            const float p1 = ex2(c[1]);
            const float p2 = ex2(c[2]);
            const float p3 = ex2(c[3]);
            l0 += p0 + p1;
            l1 += p2 + p3;
            const unsigned pa[4] = {__float_as_uint(p0), __float_as_uint(p2),
                                    __float_as_uint(p1), __float_as_uint(p3)};
#pragma unroll
            for (int dt = 0; dt < 2; dt++) {
                const float2 bv = *(const float2*)&Vs[dt * 8 + g][nt * 8 + 2 * t];
                mma_tf32(dt ? o1 : o0, pa,
                         __float_as_uint(bv.x), __float_as_uint(bv.y));
            }
        }
    }

    l0 += __shfl_xor_sync(0xFFFFFFFFu, l0, 1);
    l0 += __shfl_xor_sync(0xFFFFFFFFu, l0, 2);
    l1 += __shfl_xor_sync(0xFFFFFFFFu, l1, 1);
    l1 += __shfl_xor_sync(0xFFFFFFFFu, l1, 2);
    const float inv0 = 1.0f / l0;
    const float inv1 = 1.0f / l1;

#pragma unroll
    for (int dt = 0; dt < 2; dt++) {
        const float* o = dt ? o1 : o0;
        const int d = dt * 8 + 2 * t;
        Ob[(size_t)d       * kN + q0]     = o[0] * inv0;
        Ob[(size_t)(d + 1) * kN + q0]     = o[1] * inv0;
        Ob[(size_t)d       * kN + q0 + 8] = o[2] * inv1;
        Ob[(size_t)(d + 1) * kN + q0 + 8] = o[3] * inv1;
    }
}

// ---------------- launch ----------------
extern "C" void kernel_launch(void* const* d_in, const int* in_sizes, int n_in,
                              void* d_out, int out_size)
{
    const float* up_xyz   = (const float*)d_in[0];
    const float* xyz      = (const float*)d_in[1];
    const float* features = (const float*)d_in[2];
    const float* gfeat    = (const float*)d_in[3];
    const float* fp1_W = (const float*)d_in[4];
    const float* fp1_b = (const float*)d_in[5];
    const float* fp1_g = (const float*)d_in[6];
    const float* fp1_be= (const float*)d_in[7];
    const float* fp2_W = (const float*)d_in[8];
    const float* fp2_b = (const float*)d_in[9];
    const float* fp2_g = (const float*)d_in[10];
    const float* fp2_be= (const float*)d_in[11];
    const float* qm_W  = (const float*)d_in[12];
    const float* qm_b  = (const float*)d_in[13];
    const float* qm_g  = (const float*)d_in[14];
    const float* qm_be = (const float*)d_in[15];
    const float* fu_W  = (const float*)d_in[16];
    const float* fu_b  = (const float*)d_in[17];
    const float* fu_g  = (const float*)d_in[18];
    const float* fu_be = (const float*)d_in[19];
    const float* Wq    = (const float*)d_in[20];
    const float* Wk    = (const float*)d_in[21];
    const float* Wv    = (const float*)d_in[22];
    const float* Wp    = (const float*)d_in[23];
    const float* bp    = (const float*)d_in[24];
    const float* om_W  = (const float*)d_in[25];
    const float* om_b  = (const float*)d_in[26];
    const float* om_g  = (const float*)d_in[27];
    const float* om_be = (const float*)d_in[28];

    float *interp, *h1, *nf, *qf, *vf, *Q, *K, *V, *O, *y, *gb, *w;
    int* idx;
    cudaGetSymbolAddress((void**)&interp, g_interp);
    cudaGetSymbolAddress((void**)&h1,     g_h1);
    cudaGetSymbolAddress((void**)&nf,     g_nf);
    cudaGetSymbolAddress((void**)&qf,     g_qf);
    cudaGetSymbolAddress((void**)&vf,     g_vf);
    cudaGetSymbolAddress((void**)&Q,      g_Q);
    cudaGetSymbolAddress((void**)&K,      g_K);
    cudaGetSymbolAddress((void**)&V,      g_V);
    cudaGetSymbolAddress((void**)&O,      g_O);
    cudaGetSymbolAddress((void**)&y,      g_y);
    cudaGetSymbolAddress((void**)&gb,     g_gb);
    cudaGetSymbolAddress((void**)&idx,    g_idx);
    cudaGetSymbolAddress((void**)&w,      g_w);

    // 0) pre-split all weights into transposed, ic-paired bf16 hi/lo
    PSArgs ps;
    ps.src[0] = fp1_W; ps.off[0] = OFF_FP1; ps.OC[0] = kCIN; ps.IC[0] = kCIN;
    ps.src[1] = fp2_W; ps.off[1] = OFF_FP2; ps.OC[1] = kCFP; ps.IC[1] = kCIN;
    ps.src[2] = qm_W;  ps.off[2] = OFF_QM;  ps.OC[2] = kC;   ps.IC[2] = kCFP;
    ps.src[3] = Wq;    ps.off[3] = OFF_WQ;  ps.OC[3] = kC;   ps.IC[3] = kC;
    ps.src[4] = Wk;    ps.off[4] = OFF_WK;  ps.OC[4] = kC;   ps.IC[4] = kC;
    ps.src[5] = Wv;    ps.off[5] = OFF_WV;  ps.OC[5] = kC;   ps.IC[5] = kC;
    ps.src[6] = Wp;    ps.off[6] = OFF_WP;  ps.OC[6] = kC;   ps.IC[6] = kC;
    ps.src[7] = om_W;  ps.off[7] = OFF_OM;  ps.OC[7] = kC;   ps.IC[7] = kC;
    presplit_kernel<<<dim3(32, 8), 256>>>(ps);

    // 1) three_nn + weights
    knn_kernel<<<dim3(kN / 128, kB), 128>>>(up_xyz, xyz, idx, w);
    // 2) inverse-distance interpolation -> (B,256,N)
    interp_kernel<<<dim3(kN / 256, kCIN, kB), 256>>>(features, idx, w, interp);
    // 3) fp mlp: CBL 256->256, CBL 256->128
    gemmb<<<dim3(kN / 64, kCIN / 128, kB), 256>>>(OFF_FP1, interp, h1,
                                                  fp1_b, fp1_g, fp1_be, nullptr, kCIN, kCIN, 1);
    gemmb<<<dim3(kN / 64, 1, kB), 256>>>(OFF_FP2, h1, nf,
                                         fp2_b, fp2_g, fp2_be, nullptr, kCFP, kCIN, 1);
    // 4) q_feat = CBL 128->128
    gemmb<<<dim3(kN / 64, 1, kB), 256>>>(OFF_QM, nf, qf,
                                         qm_b, qm_g, qm_be, nullptr, kC, kCFP, 1);
    // 5) v_feat via collapsed global-feature bias
    gbias_kernel<<<kB, kC>>>(fu_W, gfeat, gb);
    vfeat_kernel<<<dim3(kN / 256, kC, kB), 256>>>(fu_W, fu_b, fu_g, fu_be, gb, up_xyz, vf);
    // 6) fused Q/K/V projections
    qkvb<<<dim3(kN / 64, 3, kB), 256>>>(qf, vf, Q, K, V);
    // 7) attention (tf32 tensor-core flash, no-max softmax)
    attn_mma<<<dim3(kN / 64, kB * kH), 128>>>(Q, K, V, O);
    // 8) proj + residual add (y = qf + Wp@O + bp)
    gemmb<<<dim3(kN / 64, 1, kB), 256>>>(OFF_WP, O, y,
                                         bp, nullptr, nullptr, qf, kC, kC, 0);
    // 9) out = CBL(y)
    gemmb<<<dim3(kN / 64, 1, kB), 256>>>(OFF_OM, y, (float*)d_out,
                                         om_b, om_g, om_be, nullptr, kC, kC, 1);
}

// round 12
// speedup vs baseline: 1.5001x; 1.1674x over previous
#include <cuda_runtime.h>
#include <cuda_bf16.h>
#include <math.h>

// ---------------- problem constants ----------------
constexpr int kB   = 8;
constexpr int kN   = 2048;
constexpr int kM   = 512;
constexpr int kCIN = 256;
constexpr int kCFP = 128;
constexpr int kC   = 128;   // C_OUT
constexpr int kCG  = 512;
constexpr int kH   = 8;
constexpr int kD   = 16;    // head dim

// ---------------- scratch (no allocation allowed) ----------------
__device__ float g_interp[kB * kCIN * kN];
__device__ float g_h1    [kB * kCIN * kN];
__device__ float g_nf    [kB * kCFP * kN];
__device__ float g_qf    [kB * kC   * kN];
__device__ float g_vf    [kB * kC   * kN];
__device__ float g_Q     [kB * kC   * kN];
__device__ float g_K     [kB * kC   * kN];
__device__ float g_V     [kB * kC   * kN];
__device__ float g_O     [kB * kC   * kN];
__device__ float g_y     [kB * kC   * kN];
__device__ float g_gb    [kB * kC];
__device__ int   g_idx   [kB * kN * 3];
__device__ float g_w     [kB * kN * 3];

// pre-split weights in MMA A-fragment layout (bf16 hi/lo)
constexpr int OFF_FP1 = 0;                 // 256x256
constexpr int OFF_FP2 = OFF_FP1 + 65536;   // 128x256
constexpr int OFF_QM  = OFF_FP2 + 32768;   // 128x128
constexpr int OFF_WQ  = OFF_QM  + 16384;
constexpr int OFF_WK  = OFF_WQ  + 16384;
constexpr int OFF_WV  = OFF_WK  + 16384;
constexpr int OFF_WP  = OFF_WV  + 16384;
constexpr int OFF_OM  = OFF_WP  + 16384;
constexpr int W_TOTAL = OFF_OM  + 16384;
__device__ __align__(16) __nv_bfloat16 g_whi16[W_TOTAL];
__device__ __align__(16) __nv_bfloat16 g_wlo16[W_TOTAL];

// ---------------- helpers ----------------
__device__ __forceinline__ float ex2(float x) {
    float y;
    asm("ex2.approx.f32 %0, %1;" : "=f"(y) : "f"(x));
    return y;
}
__device__ __forceinline__ unsigned cvt_tf32(float f) {
    unsigned u;
    asm("cvt.rna.tf32.f32 %0, %1;" : "=r"(u) : "f"(f));
    return u;
}
__device__ __forceinline__ void mma_tf32(float c[4], const unsigned a[4],
                                         unsigned b0, unsigned b1) {
    asm volatile(
        "mma.sync.aligned.m16n8k8.row.col.f32.tf32.tf32.f32 "
        "{%0,%1,%2,%3}, {%4,%5,%6,%7}, {%8,%9}, {%0,%1,%2,%3};"
        : "+f"(c[0]), "+f"(c[1]), "+f"(c[2]), "+f"(c[3])
        : "r"(a[0]), "r"(a[1]), "r"(a[2]), "r"(a[3]), "r"(b0), "r"(b1));
}
__device__ __forceinline__ void mma_bf16_u4(float c[4], uint4 a,
                                            unsigned b0, unsigned b1) {
    asm volatile(
        "mma.sync.aligned.m16n8k16.row.col.f32.bf16.bf16.f32 "
        "{%0,%1,%2,%3}, {%4,%5,%6,%7}, {%8,%9}, {%0,%1,%2,%3};"
        : "+f"(c[0]), "+f"(c[1]), "+f"(c[2]), "+f"(c[3])
        : "r"(a.x), "r"(a.y), "r"(a.z), "r"(a.w), "r"(b0), "r"(b1));
}
__device__ __forceinline__ void split_pair(float a, float b, unsigned& hi, unsigned& lo) {
    const __nv_bfloat16 ha = __float2bfloat16(a);
    const __nv_bfloat16 hb = __float2bfloat16(b);
    const __nv_bfloat16 la = __float2bfloat16(a - __bfloat162float(ha));
    const __nv_bfloat16 lb = __float2bfloat16(b - __bfloat162float(hb));
    const __nv_bfloat162 h2 = __halves2bfloat162(ha, hb);
    const __nv_bfloat162 l2 = __halves2bfloat162(la, lb);
    hi = *(const unsigned*)&h2;
    lo = *(const unsigned*)&l2;
}

// ---------------- weight pre-split into fragment layout ----------------
// Frag element index for W[oc][ic] (A = W, row=oc(m), col=ic(k)):
//   kk = ic>>4, p = (ic&15)>>1, h = ic&1, oc16 = oc>>4, ocl = oc&15
//   lane = (ocl&7)*4 + (p&3), word = ((p>>2)<<1) | (ocl>>3)
//   idx  = (((kk*(OC/16) + oc16)*32 + lane)*4 + word)*2 + h
struct PSArgs {
    const float* src[8];
    int off[8];
    int OC[8];
    int IC[8];
};
__global__ __launch_bounds__(256) void presplit_kernel(PSArgs a) {
    const int s  = blockIdx.y;
    const int OC = a.OC[s], IC = a.IC[s];
    const int n  = OC * IC;
    __nv_bfloat16* hi = g_whi16 + a.off[s];
    __nv_bfloat16* lo = g_wlo16 + a.off[s];
    for (int i = blockIdx.x * 256 + threadIdx.x; i < n; i += gridDim.x * 256) {
        const int oc = i / IC, ic = i - oc * IC;
        const float x = a.src[s][i];
        const __nv_bfloat16 h = __float2bfloat16(x);
        const __nv_bfloat16 l = __float2bfloat16(x - __bfloat162float(h));
        const int kk  = ic >> 4, kl = ic & 15;
        const int p   = kl >> 1, hh = kl & 1;
        const int o16 = oc >> 4, ocl = oc & 15;
        const int lane = (ocl & 7) * 4 + (p & 3);
        const int word = ((p >> 2) << 1) | (ocl >> 3);
        const size_t idx = ((((size_t)kk * (OC >> 4) + o16) * 32 + lane) * 4 + word) * 2 + hh;
        hi[idx] = h;
        lo[idx] = l;
    }
}

// ---------------- three_nn ----------------
__global__ __launch_bounds__(128) void knn_kernel(
    const float* __restrict__ up_xyz, const float* __restrict__ xyz,
    int* __restrict__ idxo, float* __restrict__ wo)
{
    __shared__ float sx[kM * 3];
    const int b = blockIdx.y;
    for (int i = threadIdx.x; i < kM * 3; i += 128) sx[i] = xyz[b * kM * 3 + i];
    __syncthreads();

    const int n = blockIdx.x * 128 + threadIdx.x;
    const float px = up_xyz[(b * kN + n) * 3 + 0];
    const float py = up_xyz[(b * kN + n) * 3 + 1];
    const float pz = up_xyz[(b * kN + n) * 3 + 2];

    float d0 = 1e30f, d1 = 1e30f, d2 = 1e30f;
    int   i0 = 0,     i1 = 0,     i2 = 0;
    for (int m = 0; m < kM; m++) {
        float dx = sx[m * 3 + 0] - px;
        float dy = sx[m * 3 + 1] - py;
        float dz = sx[m * 3 + 2] - pz;
        float d  = dx * dx + dy * dy + dz * dz;
        if (d < d2) {
            if (d < d1) {
                if (d < d0) { d2 = d1; i2 = i1; d1 = d0; i1 = i0; d0 = d; i0 = m; }
                else        { d2 = d1; i2 = i1; d1 = d;  i1 = m; }
            } else          { d2 = d;  i2 = m; }
        }
    }
    d0 = fmaxf(d0, 1e-10f); d1 = fmaxf(d1, 1e-10f); d2 = fmaxf(d2, 1e-10f);
    float r0 = 1.0f / d0, r1 = 1.0f / d1, r2 = 1.0f / d2;
    float s  = r0 + r1 + r2;
    const int base = (b * kN + n) * 3;
    idxo[base] = i0; idxo[base + 1] = i1; idxo[base + 2] = i2;
    wo[base] = r0 / s; wo[base + 1] = r1 / s; wo[base + 2] = r2 / s;
}

// ---------------- interpolation with smem-cached feature row ----------------
__global__ __launch_bounds__(256) void interp_kernel(
    const float* __restrict__ feat, const int* __restrict__ idx3,
    const float* __restrict__ w3, float* __restrict__ out)
{
    __shared__ float fs[kM];
    const int b = blockIdx.z, c = blockIdx.y;
    const float* f = feat + ((size_t)b * kCIN + c) * kM;
    fs[threadIdx.x]       = f[threadIdx.x];
    fs[threadIdx.x + 256] = f[threadIdx.x + 256];
    __syncthreads();

    const int n = blockIdx.x * 256 + threadIdx.x;
    const int base = (b * kN + n) * 3;
    const int j0 = idx3[base], j1 = idx3[base + 1], j2 = idx3[base + 2];
    const float w0 = w3[base], w1 = w3[base + 1], w2 = w3[base + 2];
    out[((size_t)b * kCIN + c) * kN + n] = w0 * fs[j0] + w1 * fs[j1] + w2 * fs[j2];
}

// ---------------- 3xBF16 GEMM: frag-layout W from global, X in smem ----------------
// 128oc x 64n tile, 256 threads (warps: 4 oc-tiles x 2 n-halves).
__device__ __forceinline__ void gemmb_tile(
    const uint4* __restrict__ FragHi, const uint4* __restrict__ FragLo,
    const float* __restrict__ Xb, float* __restrict__ Yb,
    int oc16stride, int oc16base, int IC, int n0,
    const float* bias, const float* gamma, const float* beta,
    const float* addB, int relu,
    unsigned (*Xsh)[72], unsigned (*Xsl)[72])
{
    const int tid  = threadIdx.x;
    const int w    = tid >> 5;
    const int lane = tid & 31;
    const int g    = lane >> 2;
    const int t    = lane & 3;
    const int ocw  = (w & 3) * 32;
    const int nw   = (w >> 2) * 32;
    const int oc16w = oc16base + (w & 3) * 2;

    const int xp = tid >> 4;            // X loader pair-row 0..15
    const int xc = (tid & 15) * 4;      // X loader col group (4 words)

    float c[2][4][4];
#pragma unroll
    for (int i = 0; i < 2; i++)
#pragma unroll
        for (int j = 0; j < 4; j++)
#pragma unroll
            for (int r = 0; r < 4; r++) c[i][j][r] = 0.0f;

    for (int k0 = 0; k0 < IC; k0 += 32) {
        // stage next X slice in registers before the WAR sync
        const float* xr0 = Xb + (size_t)(k0 + 2 * xp)     * kN + n0 + xc;
        const float* xr1 = Xb + (size_t)(k0 + 2 * xp + 1) * kN + n0 + xc;
        const float4 xa = *(const float4*)(xr0);
        const float4 xb = *(const float4*)(xr1);
        __syncthreads();
        split_pair(xa.x, xb.x, Xsh[xp][xc + 0], Xsl[xp][xc + 0]);
        split_pair(xa.y, xb.y, Xsh[xp][xc + 1], Xsl[xp][xc + 1]);
        split_pair(xa.z, xb.z, Xsh[xp][xc + 2], Xsl[xp][xc + 2]);
        split_pair(xa.w, xb.w, Xsh[xp][xc + 3], Xsl[xp][xc + 3]);
        __syncthreads();

#pragma unroll
        for (int kc = 0; kc < 2; kc++) {
            const int kk = (k0 >> 4) + kc;
            const int r0 = kc * 8 + t, r1 = kc * 8 + t + 4;
            uint4 ahi[2], alo[2];
#pragma unroll
            for (int i = 0; i < 2; i++) {
                const size_t fidx = ((size_t)kk * oc16stride + oc16w + i) * 32 + lane;
                ahi[i] = FragHi[fidx];
                alo[i] = FragLo[fidx];
            }
#pragma unroll
            for (int j = 0; j < 4; j++) {
                const int nc = nw + j * 8 + g;
                const unsigned bh0 = Xsh[r0][nc];
                const unsigned bh1 = Xsh[r1][nc];
                const unsigned bl0 = Xsl[r0][nc];
                const unsigned bl1 = Xsl[r1][nc];
#pragma unroll
                for (int i = 0; i < 2; i++) {
                    mma_bf16_u4(c[i][j], ahi[i], bh0, bh1);
                    mma_bf16_u4(c[i][j], alo[i], bh0, bh1);
                    mma_bf16_u4(c[i][j], ahi[i], bl0, bl1);
                }
            }
        }
    }

    const float rs = rsqrtf(1.0f + 1e-5f);
#pragma unroll
    for (int i = 0; i < 2; i++) {
#pragma unroll
        for (int half = 0; half < 2; half++) {
            const int oc = ocw + i * 16 + g + half * 8;
            const float bi = bias  ? bias[oc]       : 0.0f;
            const float sc = gamma ? gamma[oc] * rs : 1.0f;
            const float bb = gamma ? beta[oc]       : 0.0f;
#pragma unroll
            for (int j = 0; j < 4; j++) {
                const int nc = n0 + nw + j * 8 + 2 * t;
                float v0 = fmaf(c[i][j][half * 2]     + bi, sc, bb);
                float v1 = fmaf(c[i][j][half * 2 + 1] + bi, sc, bb);
                if (addB) {
                    const float2 ad = *(const float2*)&addB[(size_t)oc * kN + nc];
                    v0 += ad.x; v1 += ad.y;
                }
                if (relu) { v0 = fmaxf(v0, 0.0f); v1 = fmaxf(v1, 0.0f); }
                *(float2*)&Yb[(size_t)oc * kN + nc] = make_float2(v0, v1);
            }
        }
    }
}

__global__ __launch_bounds__(256, 2) void gemmb(
    int woff, const float* __restrict__ X, float* __restrict__ Y,
    const float* __restrict__ bias, const float* __restrict__ gamma,
    const float* __restrict__ beta, const float* __restrict__ add,
    int OC, int IC, int relu)
{
    __shared__ unsigned Xsh[16][72];
    __shared__ unsigned Xsl[16][72];
    const int b   = blockIdx.z;
    const int n0  = blockIdx.x * 64;
    const int oc0 = blockIdx.y * 128;
    gemmb_tile((const uint4*)(g_whi16 + woff),
               (const uint4*)(g_wlo16 + woff),
               X + (size_t)b * IC * kN,
               Y + ((size_t)b * OC + oc0) * kN,
               OC >> 4, oc0 >> 4, IC, n0,
               bias  ? bias  + oc0 : nullptr,
               gamma ? gamma + oc0 : nullptr,
               beta  ? beta  + oc0 : nullptr,
               add   ? add + ((size_t)b * OC + oc0) * kN : nullptr,
               relu, Xsh, Xsl);
}

__global__ __launch_bounds__(256, 2) void qkvb(
    const float* __restrict__ qf, const float* __restrict__ vf,
    float* __restrict__ Q, float* __restrict__ K, float* __restrict__ V)
{
    __shared__ unsigned Xsh[16][72];
    __shared__ unsigned Xsl[16][72];
    const int b = blockIdx.z;
    const int y = blockIdx.y;
    const int off = (y == 0) ? OFF_WQ : (y == 1) ? OFF_WK : OFF_WV;
    const float* X = ((y == 0) ? qf : vf) + (size_t)b * kC * kN;
    float*       Y = ((y == 0) ? Q : (y == 1) ? K : V) + (size_t)b * kC * kN;
    gemmb_tile((const uint4*)(g_whi16 + off),
               (const uint4*)(g_wlo16 + off),
               X, Y, kC >> 4, 0, kC, blockIdx.x * 64,
               nullptr, nullptr, nullptr, nullptr, 0, Xsh, Xsl);
}

// ---------------- v_feat helpers ----------------
__global__ void gbias_kernel(const float* __restrict__ fuW, const float* __restrict__ gf,
                             float* __restrict__ gb)
{
    const int b = blockIdx.x, c = threadIdx.x;
    const float* w = fuW + (size_t)c * (3 + kCG) + 3;
    const float* g = gf + b * kCG;
    float s = 0.0f;
    for (int j = 0; j < kCG; j++) s = fmaf(w[j], g[j], s);
    gb[b * kC + c] = s;
}

__global__ void vfeat_kernel(
    const float* __restrict__ fuW, const float* __restrict__ fub,
    const float* __restrict__ fug, const float* __restrict__ fube,
    const float* __restrict__ gb, const float* __restrict__ up_xyz,
    float* __restrict__ vf)
{
    const int b = blockIdx.z, c = blockIdx.y;
    const int n = blockIdx.x * 256 + threadIdx.x;
    const float w0 = fuW[c * (3 + kCG) + 0];
    const float w1 = fuW[c * (3 + kCG) + 1];
    const float w2 = fuW[c * (3 + kCG) + 2];
    const float x = up_xyz[(b * kN + n) * 3 + 0];
    const float y = up_xyz[(b * kN + n) * 3 + 1];
    const float z = up_xyz[(b * kN + n) * 3 + 2];
    float a = gb[b * kC + c] + fub[c] + w0 * x + w1 * y + w2 * z;
    const float rs = rsqrtf(1.0f + 1e-5f);
    a = fmaf(a, fug[c] * rs, fube[c]);
    vf[((size_t)b * kC + c) * kN + n] = fmaxf(a, 0.0f);
}

// ---------------- tf32 MMA flash attention: 128 q/block, 8 warps ----------------
__global__ __launch_bounds__(256) void attn_mma(
    const float* __restrict__ Q, const float* __restrict__ K,
    const float* __restrict__ V, float* __restrict__ O)
{
    __shared__ float Ks[kD][72];
    __shared__ float Vs[kD][72];
    const int bh   = blockIdx.y;
    const int tid  = threadIdx.x;
    const int warp = tid >> 5;
    const int lane = tid & 31;
    const int g    = lane >> 2;
    const int t    = lane & 3;

    const float* Qb = Q + (size_t)bh * kD * kN;
    const float* Kb = K + (size_t)bh * kD * kN;
    const float* Vb = V + (size_t)bh * kD * kN;
    float*       Ob = O + (size_t)bh * kD * kN;

    const float ALPHA = 0.25f * 1.44269504088896340736f;
    const int q0 = blockIdx.x * 128 + warp * 16 + g;

    unsigned aq[2][4];
#pragma unroll
    for (int ks = 0; ks < 2; ks++) {
        aq[ks][0] = cvt_tf32(Qb[(size_t)(ks * 8 + t)     * kN + q0]     * ALPHA);
        aq[ks][1] = cvt_tf32(Qb[(size_t)(ks * 8 + t)     * kN + q0 + 8] * ALPHA);
        aq[ks][2] = cvt_tf32(Qb[(size_t)(ks * 8 + t + 4) * kN + q0]     * ALPHA);
        aq[ks][3] = cvt_tf32(Qb[(size_t)(ks * 8 + t + 4) * kN + q0 + 8] * ALPHA);
    }

    float o0[4] = {0.f, 0.f, 0.f, 0.f};
    float o1[4] = {0.f, 0.f, 0.f, 0.f};
    float l0 = 0.f, l1 = 0.f;

    const int ld_d = tid >> 4;           // 0..15
    const int ld_k = (tid & 15) * 4;     // 0..60

    for (int kt = 0; kt < kN / 64; kt++) {
        const int k0 = kt * 64;
        __syncthreads();
        *(float4*)&Ks[ld_d][ld_k] = *(const float4*)&Kb[(size_t)ld_d * kN + k0 + ld_k];
        *(float4*)&Vs[ld_d][ld_k] = *(const float4*)&Vb[(size_t)ld_d * kN + k0 + ld_k];
        __syncthreads();

#pragma unroll
        for (int nt = 0; nt < 8; nt++) {
            float c[4] = {0.f, 0.f, 0.f, 0.f};
#pragma unroll
            for (int ks = 0; ks < 2; ks++) {
                const unsigned kb0 = __float_as_uint(Ks[ks * 8 + t][nt * 8 + g]);
                const unsigned kb1 = __float_as_uint(Ks[ks * 8 + t + 4][nt * 8 + g]);
                mma_tf32(c, aq[ks], kb0, kb1);
            }
            const float p0 = ex2(c[0]);
            const float p1 = ex2(c[1]);
            const float p2 = ex2(c[2]);
            const float p3 = ex2(c[3]);
            l0 += p0 + p1;
            l1 += p2 + p3;
            const unsigned pa[4] = {__float_as_uint(p0), __float_as_uint(p2),
                                    __float_as_uint(p1), __float_as_uint(p3)};
#pragma unroll
            for (int dt = 0; dt < 2; dt++) {
                const float2 bv = *(const float2*)&Vs[dt * 8 + g][nt * 8 + 2 * t];
                mma_tf32(dt ? o1 : o0, pa,
                         __float_as_uint(bv.x), __float_as_uint(bv.y));
            }
        }
    }

    l0 += __shfl_xor_sync(0xFFFFFFFFu, l0, 1);
    l0 += __shfl_xor_sync(0xFFFFFFFFu, l0, 2);
    l1 += __shfl_xor_sync(0xFFFFFFFFu, l1, 1);
    l1 += __shfl_xor_sync(0xFFFFFFFFu, l1, 2);
    const float inv0 = 1.0f / l0;
    const float inv1 = 1.0f / l1;

#pragma unroll
    for (int dt = 0; dt < 2; dt++) {
        const float* o = dt ? o1 : o0;
        const int d = dt * 8 + 2 * t;
        Ob[(size_t)d       * kN + q0]     = o[0] * inv0;
        Ob[(size_t)(d + 1) * kN + q0]     = o[1] * inv0;
        Ob[(size_t)d       * kN + q0 + 8] = o[2] * inv1;
        Ob[(size_t)(d + 1) * kN + q0 + 8] = o[3] * inv1;
    }
}

// ---------------- launch ----------------
extern "C" void kernel_launch(void* const* d_in, const int* in_sizes, int n_in,
                              void* d_out, int out_size)
{
    const float* up_xyz   = (const float*)d_in[0];
    const float* xyz      = (const float*)d_in[1];
    const float* features = (const float*)d_in[2];
    const float* gfeat    = (const float*)d_in[3];
    const float* fp1_W = (const float*)d_in[4];
    const float* fp1_b = (const float*)d_in[5];
    const float* fp1_g = (const float*)d_in[6];
    const float* fp1_be= (const float*)d_in[7];
    const float* fp2_W = (const float*)d_in[8];
    const float* fp2_b = (const float*)d_in[9];
    const float* fp2_g = (const float*)d_in[10];
    const float* fp2_be= (const float*)d_in[11];
    const float* qm_W  = (const float*)d_in[12];
    const float* qm_b  = (const float*)d_in[13];
    const float* qm_g  = (const float*)d_in[14];
    const float* qm_be = (const float*)d_in[15];
    const float* fu_W  = (const float*)d_in[16];
    const float* fu_b  = (const float*)d_in[17];
    const float* fu_g  = (const float*)d_in[18];
    const float* fu_be = (const float*)d_in[19];
    const float* Wq    = (const float*)d_in[20];
    const float* Wk    = (const float*)d_in[21];
    const float* Wv    = (const float*)d_in[22];
    const float* Wp    = (const float*)d_in[23];
    const float* bp    = (const float*)d_in[24];
    const float* om_W  = (const float*)d_in[25];
    const float* om_b  = (const float*)d_in[26];
    const float* om_g  = (const float*)d_in[27];
    const float* om_be = (const float*)d_in[28];

    float *interp, *h1, *nf, *qf, *vf, *Q, *K, *V, *O, *y, *gb, *w;
    int* idx;
    cudaGetSymbolAddress((void**)&interp, g_interp);
    cudaGetSymbolAddress((void**)&h1,     g_h1);
    cudaGetSymbolAddress((void**)&nf,     g_nf);
    cudaGetSymbolAddress((void**)&qf,     g_qf);
    cudaGetSymbolAddress((void**)&vf,     g_vf);
    cudaGetSymbolAddress((void**)&Q,      g_Q);
    cudaGetSymbolAddress((void**)&K,      g_K);
    cudaGetSymbolAddress((void**)&V,      g_V);
    cudaGetSymbolAddress((void**)&O,      g_O);
    cudaGetSymbolAddress((void**)&y,      g_y);
    cudaGetSymbolAddress((void**)&gb,     g_gb);
    cudaGetSymbolAddress((void**)&idx,    g_idx);
    cudaGetSymbolAddress((void**)&w,      g_w);

    // 0) pre-split all weights into fragment-layout bf16 hi/lo
    PSArgs ps;
    ps.src[0] = fp1_W; ps.off[0] = OFF_FP1; ps.OC[0] = kCIN; ps.IC[0] = kCIN;
    ps.src[1] = fp2_W; ps.off[1] = OFF_FP2; ps.OC[1] = kCFP; ps.IC[1] = kCIN;
    ps.src[2] = qm_W;  ps.off[2] = OFF_QM;  ps.OC[2] = kC;   ps.IC[2] = kCFP;
    ps.src[3] = Wq;    ps.off[3] = OFF_WQ;  ps.OC[3] = kC;   ps.IC[3] = kC;
    ps.src[4] = Wk;    ps.off[4] = OFF_WK;  ps.OC[4] = kC;   ps.IC[4] = kC;
    ps.src[5] = Wv;    ps.off[5] = OFF_WV;  ps.OC[5] = kC;   ps.IC[5] = kC;
    ps.src[6] = Wp;    ps.off[6] = OFF_WP;  ps.OC[6] = kC;   ps.IC[6] = kC;
    ps.src[7] = om_W;  ps.off[7] = OFF_OM;  ps.OC[7] = kC;   ps.IC[7] = kC;
    presplit_kernel<<<dim3(32, 8), 256>>>(ps);

    // 1) three_nn + weights
    knn_kernel<<<dim3(kN / 128, kB), 128>>>(up_xyz, xyz, idx, w);
    // 2) inverse-distance interpolation -> (B,256,N)
    interp_kernel<<<dim3(kN / 256, kCIN, kB), 256>>>(features, idx, w, interp);
    // 3) fp mlp: CBL 256->256, CBL 256->128
    gemmb<<<dim3(kN / 64, kCIN / 128, kB), 256>>>(OFF_FP1, interp, h1,
                                                  fp1_b, fp1_g, fp1_be, nullptr, kCIN, kCIN, 1);
    gemmb<<<dim3(kN / 64, 1, kB), 256>>>(OFF_FP2, h1, nf,
                                         fp2_b, fp2_g, fp2_be, nullptr, kCFP, kCIN, 1);
    // 4) q_feat = CBL 128->128
    gemmb<<<dim3(kN / 64, 1, kB), 256>>>(OFF_QM, nf, qf,
                                         qm_b, qm_g, qm_be, nullptr, kC, kCFP, 1);
    // 5) v_feat via collapsed global-feature bias
    gbias_kernel<<<kB, kC>>>(fu_W, gfeat, gb);
    vfeat_kernel<<<dim3(kN / 256, kC, kB), 256>>>(fu_W, fu_b, fu_g, fu_be, gb, up_xyz, vf);
    // 6) fused Q/K/V projections
    qkvb<<<dim3(kN / 64, 3, kB), 256>>>(qf, vf, Q, K, V);
    // 7) attention (tf32 tensor-core flash, no-max softmax, 128 q/block)
    attn_mma<<<dim3(kN / 128, kB * kH), 256>>>(Q, K, V, O);
    // 8) proj + residual add (y = qf + Wp@O + bp)
    gemmb<<<dim3(kN / 64, 1, kB), 256>>>(OFF_WP, O, y,
                                         bp, nullptr, nullptr, qf, kC, kC, 0);
    // 9) out = CBL(y)
    gemmb<<<dim3(kN / 64, 1, kB), 256>>>(OFF_OM, y, (float*)d_out,
                                         om_b, om_g, om_be, nullptr, kC, kC, 1);
}

// round 13
// speedup vs baseline: 1.5332x; 1.0221x over previous
#include <cuda_runtime.h>
#include <cuda_bf16.h>
#include <math.h>

// ---------------- problem constants ----------------
constexpr int kB   = 8;
constexpr int kN   = 2048;
constexpr int kM   = 512;
constexpr int kCIN = 256;
constexpr int kCFP = 128;
constexpr int kC   = 128;   // C_OUT
constexpr int kCG  = 512;
constexpr int kH   = 8;
constexpr int kD   = 16;    // head dim

// ---------------- scratch (no allocation allowed) ----------------
__device__ float g_interp[kB * kCIN * kN];
__device__ float g_h1    [kB * kCIN * kN];
__device__ float g_nf    [kB * kCFP * kN];
__device__ float g_qf    [kB * kC   * kN];
__device__ float g_vf    [kB * kC   * kN];
__device__ float g_Q     [kB * kC   * kN];
__device__ float g_K     [kB * kC   * kN];
__device__ float g_V     [kB * kC   * kN];
__device__ float g_O     [kB * kC   * kN];
__device__ float g_y     [kB * kC   * kN];
__device__ float g_gb    [kB * kC];
__device__ int   g_idx   [kB * kN * 3];
__device__ float g_w     [kB * kN * 3];

// pre-split weights in MMA A-fragment layout (bf16 hi/lo)
constexpr int OFF_FP1 = 0;                 // 256x256
constexpr int OFF_FP2 = OFF_FP1 + 65536;   // 128x256
constexpr int OFF_QM  = OFF_FP2 + 32768;   // 128x128
constexpr int OFF_WQ  = OFF_QM  + 16384;
constexpr int OFF_WK  = OFF_WQ  + 16384;
constexpr int OFF_WV  = OFF_WK  + 16384;
constexpr int OFF_WP  = OFF_WV  + 16384;
constexpr int OFF_OM  = OFF_WP  + 16384;
constexpr int W_TOTAL = OFF_OM  + 16384;
__device__ __align__(16) __nv_bfloat16 g_whi16[W_TOTAL];
__device__ __align__(16) __nv_bfloat16 g_wlo16[W_TOTAL];

// ---------------- helpers ----------------
__device__ __forceinline__ float ex2(float x) {
    float y;
    asm("ex2.approx.f32 %0, %1;" : "=f"(y) : "f"(x));
    return y;
}
__device__ __forceinline__ unsigned cvt_tf32(float f) {
    unsigned u;
    asm("cvt.rna.tf32.f32 %0, %1;" : "=r"(u) : "f"(f));
    return u;
}
__device__ __forceinline__ void mma_tf32(float c[4], const unsigned a[4],
                                         unsigned b0, unsigned b1) {
    asm volatile(
        "mma.sync.aligned.m16n8k8.row.col.f32.tf32.tf32.f32 "
        "{%0,%1,%2,%3}, {%4,%5,%6,%7}, {%8,%9}, {%0,%1,%2,%3};"
        : "+f"(c[0]), "+f"(c[1]), "+f"(c[2]), "+f"(c[3])
        : "r"(a[0]), "r"(a[1]), "r"(a[2]), "r"(a[3]), "r"(b0), "r"(b1));
}
__device__ __forceinline__ void mma_bf16_u4(float c[4], uint4 a,
                                            unsigned b0, unsigned b1) {
    asm volatile(
        "mma.sync.aligned.m16n8k16.row.col.f32.bf16.bf16.f32 "
        "{%0,%1,%2,%3}, {%4,%5,%6,%7}, {%8,%9}, {%0,%1,%2,%3};"
        : "+f"(c[0]), "+f"(c[1]), "+f"(c[2]), "+f"(c[3])
        : "r"(a.x), "r"(a.y), "r"(a.z), "r"(a.w), "r"(b0), "r"(b1));
}
__device__ __forceinline__ void split_pair(float a, float b, unsigned& hi, unsigned& lo) {
    const __nv_bfloat16 ha = __float2bfloat16(a);
    const __nv_bfloat16 hb = __float2bfloat16(b);
    const __nv_bfloat16 la = __float2bfloat16(a - __bfloat162float(ha));
    const __nv_bfloat16 lb = __float2bfloat16(b - __bfloat162float(hb));
    const __nv_bfloat162 h2 = __halves2bfloat162(ha, hb);
    const __nv_bfloat162 l2 = __halves2bfloat162(la, lb);
    hi = *(const unsigned*)&h2;
    lo = *(const unsigned*)&l2;
}

// ---------------- weight pre-split into fragment layout ----------------
struct PSArgs {
    const float* src[8];
    int off[8];
    int OC[8];
    int IC[8];
};
__global__ __launch_bounds__(256) void presplit_kernel(PSArgs a) {
    const int s  = blockIdx.y;
    const int OC = a.OC[s], IC = a.IC[s];
    const int n  = OC * IC;
    __nv_bfloat16* hi = g_whi16 + a.off[s];
    __nv_bfloat16* lo = g_wlo16 + a.off[s];
    for (int i = blockIdx.x * 256 + threadIdx.x; i < n; i += gridDim.x * 256) {
        const int oc = i / IC, ic = i - oc * IC;
        const float x = a.src[s][i];
        const __nv_bfloat16 h = __float2bfloat16(x);
        const __nv_bfloat16 l = __float2bfloat16(x - __bfloat162float(h));
        const int kk  = ic >> 4, kl = ic & 15;
        const int p   = kl >> 1, hh = kl & 1;
        const int o16 = oc >> 4, ocl = oc & 15;
        const int lane = (ocl & 7) * 4 + (p & 3);
        const int word = ((p >> 2) << 1) | (ocl >> 3);
        const size_t idx = ((((size_t)kk * (OC >> 4) + o16) * 32 + lane) * 4 + word) * 2 + hh;
        hi[idx] = h;
        lo[idx] = l;
    }
}

// ---------------- three_nn ----------------
__global__ __launch_bounds__(128) void knn_kernel(
    const float* __restrict__ up_xyz, const float* __restrict__ xyz,
    int* __restrict__ idxo, float* __restrict__ wo)
{
    __shared__ float sx[kM * 3];
    const int b = blockIdx.y;
    for (int i = threadIdx.x; i < kM * 3; i += 128) sx[i] = xyz[b * kM * 3 + i];
    __syncthreads();

    const int n = blockIdx.x * 128 + threadIdx.x;
    const float px = up_xyz[(b * kN + n) * 3 + 0];
    const float py = up_xyz[(b * kN + n) * 3 + 1];
    const float pz = up_xyz[(b * kN + n) * 3 + 2];

    float d0 = 1e30f, d1 = 1e30f, d2 = 1e30f;
    int   i0 = 0,     i1 = 0,     i2 = 0;
    for (int m = 0; m < kM; m++) {
        float dx = sx[m * 3 + 0] - px;
        float dy = sx[m * 3 + 1] - py;
        float dz = sx[m * 3 + 2] - pz;
        float d  = dx * dx + dy * dy + dz * dz;
        if (d < d2) {
            if (d < d1) {
                if (d < d0) { d2 = d1; i2 = i1; d1 = d0; i1 = i0; d0 = d; i0 = m; }
                else        { d2 = d1; i2 = i1; d1 = d;  i1 = m; }
            } else          { d2 = d;  i2 = m; }
        }
    }
    d0 = fmaxf(d0, 1e-10f); d1 = fmaxf(d1, 1e-10f); d2 = fmaxf(d2, 1e-10f);
    float r0 = 1.0f / d0, r1 = 1.0f / d1, r2 = 1.0f / d2;
    float s  = r0 + r1 + r2;
    const int base = (b * kN + n) * 3;
    idxo[base] = i0; idxo[base + 1] = i1; idxo[base + 2] = i2;
    wo[base] = r0 / s; wo[base + 1] = r1 / s; wo[base + 2] = r2 / s;
}

// ---------------- interpolation with smem-cached feature row ----------------
__global__ __launch_bounds__(256) void interp_kernel(
    const float* __restrict__ feat, const int* __restrict__ idx3,
    const float* __restrict__ w3, float* __restrict__ out)
{
    __shared__ float fs[kM];
    const int b = blockIdx.z, c = blockIdx.y;
    const float* f = feat + ((size_t)b * kCIN + c) * kM;
    fs[threadIdx.x]       = f[threadIdx.x];
    fs[threadIdx.x + 256] = f[threadIdx.x + 256];
    __syncthreads();

    const int n = blockIdx.x * 256 + threadIdx.x;
    const int base = (b * kN + n) * 3;
    const int j0 = idx3[base], j1 = idx3[base + 1], j2 = idx3[base + 2];
    const float w0 = w3[base], w1 = w3[base + 1], w2 = w3[base + 2];
    out[((size_t)b * kCIN + c) * kN + n] = w0 * fs[j0] + w1 * fs[j1] + w2 * fs[j2];
}

// ---------------- 3xBF16 GEMM: frag W from global, double-buffered X smem ----------------
// 128oc x 64n tile, 256 threads (warps: 4 oc-tiles x 2 n-halves), ONE sync per k32.
__device__ __forceinline__ void gemmb_tile(
    const uint4* __restrict__ FragHi, const uint4* __restrict__ FragLo,
    const float* __restrict__ Xb, float* __restrict__ Yb,
    int oc16stride, int oc16base, int IC, int n0,
    const float* bias, const float* gamma, const float* beta,
    const float* addB, int relu,
    unsigned (*Xsh)[16][72], unsigned (*Xsl)[16][72])
{
    const int tid  = threadIdx.x;
    const int w    = tid >> 5;
    const int lane = tid & 31;
    const int g    = lane >> 2;
    const int t    = lane & 3;
    const int ocw  = (w & 3) * 32;
    const int nw   = (w >> 2) * 32;
    const int oc16w = oc16base + (w & 3) * 2;

    const int xp = tid >> 4;            // X loader pair-row 0..15
    const int xc = (tid & 15) * 4;      // X loader col group (4 words)
    const float* xbase0 = Xb + (size_t)(2 * xp)     * kN + n0 + xc;
    const float* xbase1 = Xb + (size_t)(2 * xp + 1) * kN + n0 + xc;

    float c[2][4][4];
#pragma unroll
    for (int i = 0; i < 2; i++)
#pragma unroll
        for (int j = 0; j < 4; j++)
#pragma unroll
            for (int r = 0; r < 4; r++) c[i][j][r] = 0.0f;

    const int P = IC / 32;
    // prologue: phase 0 -> buf 0
    float4 xa = *(const float4*)(xbase0);
    float4 xb = *(const float4*)(xbase1);
    split_pair(xa.x, xb.x, Xsh[0][xp][xc + 0], Xsl[0][xp][xc + 0]);
    split_pair(xa.y, xb.y, Xsh[0][xp][xc + 1], Xsl[0][xp][xc + 1]);
    split_pair(xa.z, xb.z, Xsh[0][xp][xc + 2], Xsl[0][xp][xc + 2]);
    split_pair(xa.w, xb.w, Xsh[0][xp][xc + 3], Xsl[0][xp][xc + 3]);
    __syncthreads();

    for (int p = 0; p < P; p++) {
        const int cur = p & 1;
        if (p + 1 < P) {
            const size_t off = (size_t)(p + 1) * 32 * kN;
            xa = *(const float4*)(xbase0 + off);
            xb = *(const float4*)(xbase1 + off);
        }

        const int k0 = p * 32;
#pragma unroll
        for (int kc = 0; kc < 2; kc++) {
            const int kk = (k0 >> 4) + kc;
            const int r0 = kc * 8 + t, r1 = kc * 8 + t + 4;
            uint4 ahi[2], alo[2];
#pragma unroll
            for (int i = 0; i < 2; i++) {
                const size_t fidx = ((size_t)kk * oc16stride + oc16w + i) * 32 + lane;
                ahi[i] = FragHi[fidx];
                alo[i] = FragLo[fidx];
            }
#pragma unroll
            for (int j = 0; j < 4; j++) {
                const int nc = nw + j * 8 + g;
                const unsigned bh0 = Xsh[cur][r0][nc];
                const unsigned bh1 = Xsh[cur][r1][nc];
                const unsigned bl0 = Xsl[cur][r0][nc];
                const unsigned bl1 = Xsl[cur][r1][nc];
#pragma unroll
                for (int i = 0; i < 2; i++) {
                    mma_bf16_u4(c[i][j], ahi[i], bh0, bh1);
                    mma_bf16_u4(c[i][j], alo[i], bh0, bh1);
                    mma_bf16_u4(c[i][j], ahi[i], bl0, bl1);
                }
            }
        }

        if (p + 1 < P) {
            const int nxt = (p + 1) & 1;
            split_pair(xa.x, xb.x, Xsh[nxt][xp][xc + 0], Xsl[nxt][xp][xc + 0]);
            split_pair(xa.y, xb.y, Xsh[nxt][xp][xc + 1], Xsl[nxt][xp][xc + 1]);
            split_pair(xa.z, xb.z, Xsh[nxt][xp][xc + 2], Xsl[nxt][xp][xc + 2]);
            split_pair(xa.w, xb.w, Xsh[nxt][xp][xc + 3], Xsl[nxt][xp][xc + 3]);
            __syncthreads();
        }
    }

    const float rs = rsqrtf(1.0f + 1e-5f);
#pragma unroll
    for (int i = 0; i < 2; i++) {
#pragma unroll
        for (int half = 0; half < 2; half++) {
            const int oc = ocw + i * 16 + g + half * 8;
            const float bi = bias  ? bias[oc]       : 0.0f;
            const float sc = gamma ? gamma[oc] * rs : 1.0f;
            const float bb = gamma ? beta[oc]       : 0.0f;
#pragma unroll
            for (int j = 0; j < 4; j++) {
                const int nc = n0 + nw + j * 8 + 2 * t;
                float v0 = fmaf(c[i][j][half * 2]     + bi, sc, bb);
                float v1 = fmaf(c[i][j][half * 2 + 1] + bi, sc, bb);
                if (addB) {
                    const float2 ad = *(const float2*)&addB[(size_t)oc * kN + nc];
                    v0 += ad.x; v1 += ad.y;
                }
                if (relu) { v0 = fmaxf(v0, 0.0f); v1 = fmaxf(v1, 0.0f); }
                *(float2*)&Yb[(size_t)oc * kN + nc] = make_float2(v0, v1);
            }
        }
    }
}

__global__ __launch_bounds__(256, 2) void gemmb(
    int woff, const float* __restrict__ X, float* __restrict__ Y,
    const float* __restrict__ bias, const float* __restrict__ gamma,
    const float* __restrict__ beta, const float* __restrict__ add,
    int OC, int IC, int relu)
{
    __shared__ unsigned Xsh[2][16][72];
    __shared__ unsigned Xsl[2][16][72];
    const int b   = blockIdx.z;
    const int n0  = blockIdx.x * 64;
    const int oc0 = blockIdx.y * 128;
    gemmb_tile((const uint4*)(g_whi16 + woff),
               (const uint4*)(g_wlo16 + woff),
               X + (size_t)b * IC * kN,
               Y + ((size_t)b * OC + oc0) * kN,
               OC >> 4, oc0 >> 4, IC, n0,
               bias  ? bias  + oc0 : nullptr,
               gamma ? gamma + oc0 : nullptr,
               beta  ? beta  + oc0 : nullptr,
               add   ? add + ((size_t)b * OC + oc0) * kN : nullptr,
               relu, Xsh, Xsl);
}

__global__ __launch_bounds__(256, 2) void qkvb(
    const float* __restrict__ qf, const float* __restrict__ vf,
    float* __restrict__ Q, float* __restrict__ K, float* __restrict__ V)
{
    __shared__ unsigned Xsh[2][16][72];
    __shared__ unsigned Xsl[2][16][72];
    const int b = blockIdx.z;
    const int y = blockIdx.y;
    const int off = (y == 0) ? OFF_WQ : (y == 1) ? OFF_WK : OFF_WV;
    const float* X = ((y == 0) ? qf : vf) + (size_t)b * kC * kN;
    float*       Y = ((y == 0) ? Q : (y == 1) ? K : V) + (size_t)b * kC * kN;
    gemmb_tile((const uint4*)(g_whi16 + off),
               (const uint4*)(g_wlo16 + off),
               X, Y, kC >> 4, 0, kC, blockIdx.x * 64,
               nullptr, nullptr, nullptr, nullptr, 0, Xsh, Xsl);
}

// ---------------- v_feat helpers ----------------
__global__ void gbias_kernel(const float* __restrict__ fuW, const float* __restrict__ gf,
                             float* __restrict__ gb)
{
    const int b = blockIdx.x, c = threadIdx.x;
    const float* w = fuW + (size_t)c * (3 + kCG) + 3;
    const float* g = gf + b * kCG;
    float s = 0.0f;
    for (int j = 0; j < kCG; j++) s = fmaf(w[j], g[j], s);
    gb[b * kC + c] = s;
}

__global__ void vfeat_kernel(
    const float* __restrict__ fuW, const float* __restrict__ fub,
    const float* __restrict__ fug, const float* __restrict__ fube,
    const float* __restrict__ gb, const float* __restrict__ up_xyz,
    float* __restrict__ vf)
{
    const int b = blockIdx.z, c = blockIdx.y;
    const int n = blockIdx.x * 256 + threadIdx.x;
    const float w0 = fuW[c * (3 + kCG) + 0];
    const float w1 = fuW[c * (3 + kCG) + 1];
    const float w2 = fuW[c * (3 + kCG) + 2];
    const float x = up_xyz[(b * kN + n) * 3 + 0];
    const float y = up_xyz[(b * kN + n) * 3 + 1];
    const float z = up_xyz[(b * kN + n) * 3 + 2];
    float a = gb[b * kC + c] + fub[c] + w0 * x + w1 * y + w2 * z;
    const float rs = rsqrtf(1.0f + 1e-5f);
    a = fmaf(a, fug[c] * rs, fube[c]);
    vf[((size_t)b * kC + c) * kN + n] = fmaxf(a, 0.0f);
}

// ---------------- tf32 MMA flash attention: double-buffered K/V, one sync/tile ----------------
__global__ __launch_bounds__(256) void attn_mma(
    const float* __restrict__ Q, const float* __restrict__ K,
    const float* __restrict__ V, float* __restrict__ O)
{
    __shared__ float Ks[2][kD][72];
    __shared__ float Vs[2][kD][72];
    const int bh   = blockIdx.y;
    const int tid  = threadIdx.x;
    const int warp = tid >> 5;
    const int lane = tid & 31;
    const int g    = lane >> 2;
    const int t    = lane & 3;

    const float* Qb = Q + (size_t)bh * kD * kN;
    const float* Kb = K + (size_t)bh * kD * kN;
    const float* Vb = V + (size_t)bh * kD * kN;
    float*       Ob = O + (size_t)bh * kD * kN;

    const float ALPHA = 0.25f * 1.44269504088896340736f;
    const int q0 = blockIdx.x * 128 + warp * 16 + g;

    unsigned aq[2][4];
#pragma unroll
    for (int ks = 0; ks < 2; ks++) {
        aq[ks][0] = cvt_tf32(Qb[(size_t)(ks * 8 + t)     * kN + q0]     * ALPHA);
        aq[ks][1] = cvt_tf32(Qb[(size_t)(ks * 8 + t)     * kN + q0 + 8] * ALPHA);
        aq[ks][2] = cvt_tf32(Qb[(size_t)(ks * 8 + t + 4) * kN + q0]     * ALPHA);
        aq[ks][3] = cvt_tf32(Qb[(size_t)(ks * 8 + t + 4) * kN + q0 + 8] * ALPHA);
    }

    float o0[4] = {0.f, 0.f, 0.f, 0.f};
    float o1[4] = {0.f, 0.f, 0.f, 0.f};
    float l0 = 0.f, l1 = 0.f;

    const int ld_d = tid >> 4;           // 0..15
    const int ld_k = (tid & 15) * 4;     // 0..60
    const float* kb = Kb + (size_t)ld_d * kN + ld_k;
    const float* vb = Vb + (size_t)ld_d * kN + ld_k;

    constexpr int T = kN / 64;
    // prologue: tile 0 -> buf 0
    float4 kreg = *(const float4*)(kb);
    float4 vreg = *(const float4*)(vb);
    *(float4*)&Ks[0][ld_d][ld_k] = kreg;
    *(float4*)&Vs[0][ld_d][ld_k] = vreg;
    __syncthreads();

    for (int kt = 0; kt < T; kt++) {
        const int cur = kt & 1;
        if (kt + 1 < T) {
            kreg = *(const float4*)(kb + (kt + 1) * 64);
            vreg = *(const float4*)(vb + (kt + 1) * 64);
        }

#pragma unroll
        for (int nt = 0; nt < 8; nt++) {
            float c[4] = {0.f, 0.f, 0.f, 0.f};
#pragma unroll
            for (int ks = 0; ks < 2; ks++) {
                const unsigned kb0 = __float_as_uint(Ks[cur][ks * 8 + t][nt * 8 + g]);
                const unsigned kb1 = __float_as_uint(Ks[cur][ks * 8 + t + 4][nt * 8 + g]);
                mma_tf32(c, aq[ks], kb0, kb1);
            }
            const float p0 = ex2(c[0]);
            const float p1 = ex2(c[1]);
            const float p2 = ex2(c[2]);
            const float p3 = ex2(c[3]);
            l0 += p0 + p1;
            l1 += p2 + p3;
            const unsigned pa[4] = {__float_as_uint(p0), __float_as_uint(p2),
                                    __float_as_uint(p1), __float_as_uint(p3)};
#pragma unroll
            for (int dt = 0; dt < 2; dt++) {
                const float2 bv = *(const float2*)&Vs[cur][dt * 8 + g][nt * 8 + 2 * t];
                mma_tf32(dt ? o1 : o0, pa,
                         __float_as_uint(bv.x), __float_as_uint(bv.y));
            }
        }

        if (kt + 1 < T) {
            const int nxt = (kt + 1) & 1;
            *(float4*)&Ks[nxt][ld_d][ld_k] = kreg;
            *(float4*)&Vs[nxt][ld_d][ld_k] = vreg;
            __syncthreads();
        }
    }

    l0 += __shfl_xor_sync(0xFFFFFFFFu, l0, 1);
    l0 += __shfl_xor_sync(0xFFFFFFFFu, l0, 2);
    l1 += __shfl_xor_sync(0xFFFFFFFFu, l1, 1);
    l1 += __shfl_xor_sync(0xFFFFFFFFu, l1, 2);
    const float inv0 = 1.0f / l0;
    const float inv1 = 1.0f / l1;

#pragma unroll
    for (int dt = 0; dt < 2; dt++) {
        const float* o = dt ? o1 : o0;
        const int d = dt * 8 + 2 * t;
        Ob[(size_t)d       * kN + q0]     = o[0] * inv0;
        Ob[(size_t)(d + 1) * kN + q0]     = o[1] * inv0;
        Ob[(size_t)d       * kN + q0 + 8] = o[2] * inv1;
        Ob[(size_t)(d + 1) * kN + q0 + 8] = o[3] * inv1;
    }
}

// ---------------- launch ----------------
extern "C" void kernel_launch(void* const* d_in, const int* in_sizes, int n_in,
                              void* d_out, int out_size)
{
    const float* up_xyz   = (const float*)d_in[0];
    const float* xyz      = (const float*)d_in[1];
    const float* features = (const float*)d_in[2];
    const float* gfeat    = (const float*)d_in[3];
    const float* fp1_W = (const float*)d_in[4];
    const float* fp1_b = (const float*)d_in[5];
    const float* fp1_g = (const float*)d_in[6];
    const float* fp1_be= (const float*)d_in[7];
    const float* fp2_W = (const float*)d_in[8];
    const float* fp2_b = (const float*)d_in[9];
    const float* fp2_g = (const float*)d_in[10];
    const float* fp2_be= (const float*)d_in[11];
    const float* qm_W  = (const float*)d_in[12];
    const float* qm_b  = (const float*)d_in[13];
    const float* qm_g  = (const float*)d_in[14];
    const float* qm_be = (const float*)d_in[15];
    const float* fu_W  = (const float*)d_in[16];
    const float* fu_b  = (const float*)d_in[17];
    const float* fu_g  = (const float*)d_in[18];
    const float* fu_be = (const float*)d_in[19];
    const float* Wq    = (const float*)d_in[20];
    const float* Wk    = (const float*)d_in[21];
    const float* Wv    = (const float*)d_in[22];
    const float* Wp    = (const float*)d_in[23];
    const float* bp    = (const float*)d_in[24];
    const float* om_W  = (const float*)d_in[25];
    const float* om_b  = (const float*)d_in[26];
    const float* om_g  = (const float*)d_in[27];
    const float* om_be = (const float*)d_in[28];

    float *interp, *h1, *nf, *qf, *vf, *Q, *K, *V, *O, *y, *gb, *w;
    int* idx;
    cudaGetSymbolAddress((void**)&interp, g_interp);
    cudaGetSymbolAddress((void**)&h1,     g_h1);
    cudaGetSymbolAddress((void**)&nf,     g_nf);
    cudaGetSymbolAddress((void**)&qf,     g_qf);
    cudaGetSymbolAddress((void**)&vf,     g_vf);
    cudaGetSymbolAddress((void**)&Q,      g_Q);
    cudaGetSymbolAddress((void**)&K,      g_K);
    cudaGetSymbolAddress((void**)&V,      g_V);
    cudaGetSymbolAddress((void**)&O,      g_O);
    cudaGetSymbolAddress((void**)&y,      g_y);
    cudaGetSymbolAddress((void**)&gb,     g_gb);
    cudaGetSymbolAddress((void**)&idx,    g_idx);
    cudaGetSymbolAddress((void**)&w,      g_w);

    // 0) pre-split all weights into fragment-layout bf16 hi/lo
    PSArgs ps;
    ps.src[0] = fp1_W; ps.off[0] = OFF_FP1; ps.OC[0] = kCIN; ps.IC[0] = kCIN;
    ps.src[1] = fp2_W; ps.off[1] = OFF_FP2; ps.OC[1] = kCFP; ps.IC[1] = kCIN;
    ps.src[2] = qm_W;  ps.off[2] = OFF_QM;  ps.OC[2] = kC;   ps.IC[2] = kCFP;
    ps.src[3] = Wq;    ps.off[3] = OFF_WQ;  ps.OC[3] = kC;   ps.IC[3] = kC;
    ps.src[4] = Wk;    ps.off[4] = OFF_WK;  ps.OC[4] = kC;   ps.IC[4] = kC;
    ps.src[5] = Wv;    ps.off[5] = OFF_WV;  ps.OC[5] = kC;   ps.IC[5] = kC;
    ps.src[6] = Wp;    ps.off[6] = OFF_WP;  ps.OC[6] = kC;   ps.IC[6] = kC;
    ps.src[7] = om_W;  ps.off[7] = OFF_OM;  ps.OC[7] = kC;   ps.IC[7] = kC;
    presplit_kernel<<<dim3(32, 8), 256>>>(ps);

    // 1) three_nn + weights
    knn_kernel<<<dim3(kN / 128, kB), 128>>>(up_xyz, xyz, idx, w);
    // 2) inverse-distance interpolation -> (B,256,N)
    interp_kernel<<<dim3(kN / 256, kCIN, kB), 256>>>(features, idx, w, interp);
    // 3) fp mlp: CBL 256->256, CBL 256->128
    gemmb<<<dim3(kN / 64, kCIN / 128, kB), 256>>>(OFF_FP1, interp, h1,
                                                  fp1_b, fp1_g, fp1_be, nullptr, kCIN, kCIN, 1);
    gemmb<<<dim3(kN / 64, 1, kB), 256>>>(OFF_FP2, h1, nf,
                                         fp2_b, fp2_g, fp2_be, nullptr, kCFP, kCIN, 1);
    // 4) q_feat = CBL 128->128
    gemmb<<<dim3(kN / 64, 1, kB), 256>>>(OFF_QM, nf, qf,
                                         qm_b, qm_g, qm_be, nullptr, kC, kCFP, 1);
    // 5) v_feat via collapsed global-feature bias
    gbias_kernel<<<kB, kC>>>(fu_W, gfeat, gb);
    vfeat_kernel<<<dim3(kN / 256, kC, kB), 256>>>(fu_W, fu_b, fu_g, fu_be, gb, up_xyz, vf);
    // 6) fused Q/K/V projections
    qkvb<<<dim3(kN / 64, 3, kB), 256>>>(qf, vf, Q, K, V);
    // 7) attention (tf32 tensor-core flash, no-max softmax, 128 q/block, dbuf)
    attn_mma<<<dim3(kN / 128, kB * kH), 256>>>(Q, K, V, O);
    // 8) proj + residual add (y = qf + Wp@O + bp)
    gemmb<<<dim3(kN / 64, 1, kB), 256>>>(OFF_WP, O, y,
                                         bp, nullptr, nullptr, qf, kC, kC, 0);
    // 9) out = CBL(y)
    gemmb<<<dim3(kN / 64, 1, kB), 256>>>(OFF_OM, y, (float*)d_out,
                                         om_b, om_g, om_be, nullptr, kC, kC, 1);
}